// round 11
// baseline (speedup 1.0000x reference)
#include <cuda_runtime.h>
#include <cuda_fp16.h>
#include <cstdint>

// ----------------------------------------------------------------------------
// R10: ONE fused persistent kernel for all three GEMMs, register-pressure fixed
// (single-buffered fragments so 288-thread CTA fits without spills).
//   h = relu(x @ W_init^T + b_init)        M=32768 N=2048 K=1024   tiles 0..2047
//   o = relu(h @ W_ih^T  + b_ih + b_hh)    M=32768 N=2048 K=2048   tiles 2048..4095
//   y =       o @ W_final^T + b_final      M=32768 N=1024 K=2048   tiles 4096..5119
// fp16 mma.sync m16n8k16 + ldmatrix; cp.async.bulk + mbarrier pipeline.
// 288 threads: warps 0-7 compute (128x256 CTA tile), warp 8 = producer.
// Cross-phase deps: per-m-block counters (64 arrivals = 8 tiles x 8 warps).
// ----------------------------------------------------------------------------

#define DINLINE __device__ __forceinline__

static constexpr int DIN  = 1024;
static constexpr int DH   = 2048;
static constexpr int DACT = 1024;
static constexpr long MTOK = 32768;

static constexpr int BM = 128;
static constexpr int BN = 256;
static constexpr int BK = 64;            // 128B rows
static constexpr int STAGES = 4;
static constexpr int NTHR = 288;         // 8 compute warps + 1 producer warp

static constexpr int A_ST = BM * BK * 2;         // 16384 B
static constexpr int B_ST = BN * BK * 2;         // 32768 B
static constexpr int STG  = A_ST + B_ST;         // 49152 B
static constexpr int HDR  = 1024;
static constexpr int SMEM_TOTAL = HDR + STAGES * STG;   // 197632

static constexpr int T1 = 2048;      // GEMM1 tiles (256 m x 8 n)
static constexpr int T2 = 2048;      // GEMM2 tiles
static constexpr int T3 = 1024;      // GEMM3 tiles (256 m x 4 n)
static constexpr int TTOT = T1 + T2 + T3;   // 5120

DINLINE uint32_t smem_u32(const void* p) {
    uint32_t a;
    asm("{ .reg .u64 t; cvta.to.shared.u64 t, %1; cvt.u32.u64 %0, t; }"
        : "=r"(a) : "l"(p));
    return a;
}

#define MBARRIER_INIT(addr, cnt) \
    asm volatile("mbarrier.init.shared.b64 [%0], %1;" :: "r"(addr), "r"(cnt) : "memory")
#define MBARRIER_ARRIVE(addr) \
    asm volatile("mbarrier.arrive.shared.b64 _, [%0];" :: "r"(addr) : "memory")
#define MBARRIER_EXPECT_TX(addr, n) \
    asm volatile("mbarrier.arrive.expect_tx.shared.b64 _, [%0], %1;" :: "r"(addr), "r"(n) : "memory")

#define MBARRIER_WAIT_PARITY(mbar_smem_addr, phase_parity) do { \
    uint32_t _mbar = (uint32_t)(mbar_smem_addr); \
    uint32_t _parity = (uint32_t)(phase_parity); \
    uint32_t _done; \
    asm volatile( \
        "{\n\t" \
        ".reg .pred p;\n\t" \
        "mbarrier.try_wait.parity.shared.b64 p, [%1], %2;\n\t" \
        "selp.b32 %0, 1, 0, p;\n\t" \
        "}" \
        : "=r"(_done) : "r"(_mbar), "r"(_parity) : "memory"); \
    if (!_done) { \
        asm volatile( \
            "{\n\t" \
            ".reg .pred P1;\n\t" \
            "WAIT_LOOP_%=:\n\t" \
            "mbarrier.try_wait.parity.shared.b64 P1, [%0], %1, 0x989680;\n\t" \
            "@P1 bra.uni WAIT_DONE_%=;\n\t" \
            "bra.uni WAIT_LOOP_%=;\n\t" \
            "WAIT_DONE_%=:\n\t" \
            "}" \
            :: "r"(_mbar), "r"(_parity) : "memory"); \
    } \
} while(0)

#define BULK_G2S(dst, src, sz, mbar) \
    asm volatile("cp.async.bulk.shared::cta.global.mbarrier::complete_tx::bytes [%0], [%1], %2, [%3];" \
        :: "r"((uint32_t)(dst)), "l"(src), "r"((uint32_t)(sz)), "r"((uint32_t)(mbar)) : "memory")

DINLINE void ldsm_x4(uint32_t* r, uint32_t addr) {
    asm volatile("ldmatrix.sync.aligned.m8n8.x4.shared.b16 {%0,%1,%2,%3}, [%4];"
        : "=r"(r[0]), "=r"(r[1]), "=r"(r[2]), "=r"(r[3]) : "r"(addr));
}

DINLINE void mma_f16(float* c, const uint32_t* a, const uint32_t* b) {
    asm volatile(
        "mma.sync.aligned.m16n8k16.row.col.f32.f16.f16.f32 "
        "{%0,%1,%2,%3}, {%4,%5,%6,%7}, {%8,%9}, {%0,%1,%2,%3};"
        : "+f"(c[0]), "+f"(c[1]), "+f"(c[2]), "+f"(c[3])
        : "r"(a[0]), "r"(a[1]), "r"(a[2]), "r"(a[3]), "r"(b[0]), "r"(b[1]));
}

// ----------------------------------------------------------------------------
// Scratch + dependency counters (static device allocations -- allowed).
// ----------------------------------------------------------------------------
__device__ __half g_x [MTOK * DIN];
__device__ __half g_h [MTOK * DH];
__device__ __half g_o [MTOK * DH];
__device__ __half g_w1[(long)DH * DIN];
__device__ __half g_w2[(long)DH * DH];
__device__ __half g_w3[(long)DACT * DH];
__device__ int g_c1[256];   // h m-block ready counters (target 64)
__device__ int g_c2[256];   // o m-block ready counters (target 64)

// ----------------------------------------------------------------------------
// Fused fp32 -> fp16 + tile/swizzle pre-pass (all four tensors, one launch).
// ----------------------------------------------------------------------------
struct CvtSeg {
    const float* in;
    __half* out;
    int ng;        // granule count
    int kshift;    // log2(K/8)
    int rplog;     // log2(RP)
};

__global__ void __launch_bounds__(512, 2)
cvt_all_kernel(CvtSeg s0, CvtSeg s1, CvtSeg s2, CvtSeg s3, int total)
{
    for (int gi0 = blockIdx.x * blockDim.x + threadIdx.x; gi0 < total;
         gi0 += gridDim.x * blockDim.x) {
        CvtSeg s; int gi = gi0;
        if (gi < s0.ng) s = s0;
        else {
            gi -= s0.ng;
            if (gi < s1.ng) s = s1;
            else {
                gi -= s1.ng;
                if (gi < s2.ng) s = s2;
                else { gi -= s2.ng; s = s3; }
            }
        }
        const int gperrow = 1 << s.kshift;
        const int c8 = gi & (gperrow - 1);
        const int r  = gi >> s.kshift;
        const float4* f4 = reinterpret_cast<const float4*>(s.in);
        float4 v0 = f4[2 * (size_t)gi], v1 = f4[2 * (size_t)gi + 1];
        __half2 h0 = __floats2half2_rn(v0.x, v0.y), h1 = __floats2half2_rn(v0.z, v0.w);
        __half2 h2 = __floats2half2_rn(v1.x, v1.y), h3 = __floats2half2_rn(v1.z, v1.w);
        uint4 o = make_uint4(*reinterpret_cast<uint32_t*>(&h0), *reinterpret_cast<uint32_t*>(&h1),
                             *reinterpret_cast<uint32_t*>(&h2), *reinterpret_cast<uint32_t*>(&h3));
        const int rp = 1 << s.rplog;
        const size_t panel = (size_t)(r >> s.rplog) * (gperrow >> 3) + (c8 >> 3);
        const size_t gip   = (size_t)(r & (rp - 1)) * 8 + ((c8 & 7) ^ (r & 7));
        reinterpret_cast<uint4*>(s.out)[panel * ((size_t)rp * 8) + gip] = o;
    }
}

// tile id -> phase/operands/geometry
DINLINE void decode_tile(int t, const __half*& A, const __half*& B,
                         int& ktlog, int& ntlog, int& mt, int& nt, int& ph)
{
    int local;
    if (t < T1)            { ph = 1; local = t;           ktlog = 4; ntlog = 3; A = g_x; B = g_w1; }
    else if (t < T1 + T2)  { ph = 2; local = t - T1;      ktlog = 5; ntlog = 3; A = g_h; B = g_w2; }
    else                   { ph = 3; local = t - T1 - T2; ktlog = 5; ntlog = 2; A = g_o; B = g_w3; }
    mt = local >> ntlog;
    nt = local & ((1 << ntlog) - 1);
}

// ----------------------------------------------------------------------------
// Fused persistent 3-GEMM kernel.
// ----------------------------------------------------------------------------
__global__ void __launch_bounds__(NTHR, 1)
fused3_kernel(const float* __restrict__ b1, const float* __restrict__ bih,
              const float* __restrict__ bhh, const float* __restrict__ b3,
              float* __restrict__ out)
{
    extern __shared__ char smem[];
    const uint32_t sbase = smem_u32(smem);
    const int tid = threadIdx.x;
    const int wid = tid >> 5;
    const int lid = tid & 31;
    const int bid = blockIdx.x;
    const int grid = gridDim.x;

    // mbarriers: full[s] @ 8s, empty[s] @ 64+8s
    if (tid == 0) {
        #pragma unroll
        for (int s = 0; s < STAGES; ++s) {
            MBARRIER_INIT(sbase + 8 * s, 1);
            MBARRIER_INIT(sbase + 64 + 8 * s, 8);
        }
    }
    __syncthreads();

    const int nMy = (TTOT - bid - 1) / grid + 1;

    // ======================= producer warp (wid 8) ==========================
    if (wid == 8) {
        if (lid == 0) {
            long pGi = 0;
            for (int tl = 0; tl < nMy; ++tl) {
                const int t = bid + tl * grid;
                const __half *A, *B; int ktlog, ntlog, mt, nt, ph;
                decode_tile(t, A, B, ktlog, ntlog, mt, nt, ph);
                // dataflow dependency: spin until the A m-block is published.
                // Free-running producer warp => compute warps keep finishing
                // earlier tiles, counters advance, global progress guaranteed.
                if (ph == 2)      { while (*(volatile int*)&g_c1[mt] < 64) {} }
                else if (ph == 3) { while (*(volatile int*)&g_c2[mt] < 64) {} }
                __threadfence();   // acquire side
                const int KT = 1 << ktlog;
                for (int kt = 0; kt < KT; ++kt, ++pGi) {
                    const int s2 = (int)(pGi & 3);
                    if (pGi >= STAGES)
                        MBARRIER_WAIT_PARITY(sbase + 64 + 8 * s2,
                                             (uint32_t)(((pGi >> 2) - 1) & 1));
                    const __half* pa = A + ((size_t)mt * KT + kt) * (A_ST / 2);
                    const __half* pb = B + ((size_t)nt * KT + kt) * (B_ST / 2);
                    const uint32_t st = sbase + HDR + s2 * STG;
                    MBARRIER_EXPECT_TX(sbase + 8 * s2, STG);
                    BULK_G2S(st,        pa, A_ST, sbase + 8 * s2);
                    BULK_G2S(st + A_ST, pb, B_ST, sbase + 8 * s2);
                }
            }
        }
        return;
    }

    // ======================= compute warps (wid 0-7) ========================
    const int g   = lid >> 2;
    const int tg  = lid & 3;
    const int warpM = wid >> 2;
    const int warpN = wid & 3;

    // ldmatrix per-lane bases (swizzled granule addressing)
    const int lm   = lid >> 3;
    const int aRow = warpM * 64 + ((lm & 1) << 3) + (lid & 7);
    const int asel = lm >> 1;
    const int aXor = aRow & 7;
    const int bRow = warpN * 64 + ((lm >> 1) << 3) + (lid & 7);
    const int bsel = lm & 1;
    const int bXor = bRow & 7;
    uint32_t aBase[4], bBase[4];
    #pragma unroll
    for (int i = 0; i < 4; ++i) aBase[i] = (uint32_t)(aRow + i * 16) * 128;
    #pragma unroll
    for (int jp = 0; jp < 4; ++jp) bBase[jp] = (uint32_t)(bRow + jp * 16) * 128;

    long gi = 0;
    for (int tl = 0; tl < nMy; ++tl) {
        const int t = bid + tl * grid;
        const __half *A, *B; int ktlog, ntlog, mt, nt, ph;
        decode_tile(t, A, B, ktlog, ntlog, mt, nt, ph);
        const int KT = 1 << ktlog;
        const long m0 = (long)mt * BM;
        const int  n0 = nt * BN;

        float acc[4][8][4];
        #pragma unroll
        for (int i = 0; i < 4; ++i)
            #pragma unroll
            for (int j = 0; j < 8; ++j)
                #pragma unroll
                for (int e = 0; e < 4; ++e) acc[i][j][e] = 0.0f;

        for (int kt = 0; kt < KT; ++kt, ++gi) {
            const int s = (int)(gi & 3);
            MBARRIER_WAIT_PARITY(sbase + 8 * s, (uint32_t)((gi >> 2) & 1));

            const uint32_t sA = sbase + HDR + s * STG;
            const uint32_t sB = sA + A_ST;

            // single-buffered fragments (keeps regs under the 288-thread cap)
            #pragma unroll
            for (int kk = 0; kk < 4; ++kk) {
                uint32_t fa[4][4], fb[4][4];
                const uint32_t aoff = (uint32_t)(((kk * 2 + asel) ^ aXor) << 4);
                const uint32_t boff = (uint32_t)(((kk * 2 + bsel) ^ bXor) << 4);
                #pragma unroll
                for (int i = 0; i < 4; ++i)    ldsm_x4(fa[i],  sA + aBase[i]  + aoff);
                #pragma unroll
                for (int jp = 0; jp < 4; ++jp) ldsm_x4(fb[jp], sB + bBase[jp] + boff);
                #pragma unroll
                for (int i = 0; i < 4; ++i)
                    #pragma unroll
                    for (int j = 0; j < 8; ++j)
                        mma_f16(acc[i][j], fa[i], &fb[j >> 1][(j & 1) * 2]);
            }

            __syncwarp();
            if (lid == 0) MBARRIER_ARRIVE(sbase + 64 + 8 * s);
        }

        // ---- epilogue (phase-dependent) ------------------------------------
        const float* bias1 = (ph == 1) ? b1 : (ph == 2) ? bih : b3;
        const float* bias2 = (ph == 2) ? bhh : nullptr;
        const int N = (ph == 3) ? DACT : DH;
        const int jb0 = n0 + warpN * 64;

        #pragma unroll
        for (int j = 0; j < 8; ++j) {
            const int col = jb0 + j * 8 + 2 * tg;
            float bb0 = bias1[col], bb1 = bias1[col + 1];
            if (bias2) { bb0 += bias2[col]; bb1 += bias2[col + 1]; }
            #pragma unroll
            for (int i = 0; i < 4; ++i) {
                const long r0 = m0 + warpM * 64 + i * 16 + g;
                #pragma unroll
                for (int h = 0; h < 2; ++h) {
                    const long r = r0 + 8 * h;
                    float v0 = acc[i][j][2 * h + 0] + bb0;
                    float v1 = acc[i][j][2 * h + 1] + bb1;
                    if (ph != 3) {
                        v0 = fmaxf(v0, 0.0f); v1 = fmaxf(v1, 0.0f);
                        // swizzled 128-row panel layout (next GEMM's A operand)
                        __half2 hv = __floats2half2_rn(v0, v1);
                        __half* Cp = (ph == 1) ? g_h : g_o;
                        const size_t panel = ((size_t)(r >> 7) * (N >> 6) + (col >> 6)) << 13;
                        const size_t off = panel + (size_t)((int)(r & 127)) * 64
                                         + (size_t)(((((col >> 3) & 7) ^ ((int)r & 7)) << 3) + (col & 7));
                        *reinterpret_cast<uint32_t*>(Cp + off) =
                            *reinterpret_cast<uint32_t*>(&hv);
                    } else {
                        *reinterpret_cast<float2*>(out + (size_t)r * N + col) =
                            make_float2(v0, v1);
                    }
                }
            }
        }

        // publish: release the m-block slice this tile contributed
        if (ph != 3) {
            __threadfence();
            __syncwarp();
            if (lid == 0) {
                if (ph == 1) atomicAdd(&g_c1[mt], 1);
                else         atomicAdd(&g_c2[mt], 1);
            }
        }
    }
}

// ----------------------------------------------------------------------------
// Host launcher
// ----------------------------------------------------------------------------
extern "C" void kernel_launch(void* const* d_in, const int* in_sizes, int n_in,
                              void* d_out, int out_size)
{
    const float* x    = (const float*)d_in[0];
    const float* W1   = (const float*)d_in[1];
    const float* b1   = (const float*)d_in[2];
    const float* W2   = (const float*)d_in[3];
    const float* bih  = (const float*)d_in[4];
    const float* bhh  = (const float*)d_in[5];
    const float* W3   = (const float*)d_in[6];
    const float* b3   = (const float*)d_in[7];
    float* out = (float*)d_out;

    __half *gx, *gw1, *gw2, *gw3;
    cudaGetSymbolAddress((void**)&gx,  g_x);
    cudaGetSymbolAddress((void**)&gw1, g_w1);
    cudaGetSymbolAddress((void**)&gw2, g_w2);
    cudaGetSymbolAddress((void**)&gw3, g_w3);

    int *c1, *c2;
    cudaGetSymbolAddress((void**)&c1, g_c1);
    cudaGetSymbolAddress((void**)&c2, g_c2);
    cudaMemsetAsync(c1, 0, 256 * sizeof(int));
    cudaMemsetAsync(c2, 0, 256 * sizeof(int));

    cudaFuncSetAttribute(fused3_kernel,
                         cudaFuncAttributeMaxDynamicSharedMemorySize, SMEM_TOTAL);

    int nsm = 148;
    cudaDeviceGetAttribute(&nsm, cudaDevAttrMultiProcessorCount, 0);

    // fused pre-pass: fp32 -> fp16 into swizzled panels (single launch)
    {
        CvtSeg s0 = { x,  gx,  (int)(MTOK * (long)DIN / 8), 7, 7 };   // RP=128
        CvtSeg s1 = { W1, gw1, (int)((long)DH * DIN / 8),   7, 8 };   // RP=256
        CvtSeg s2 = { W2, gw2, (int)((long)DH * DH / 8),    8, 8 };
        CvtSeg s3 = { W3, gw3, (int)((long)DACT * DH / 8),  8, 8 };
        const int total = s0.ng + s1.ng + s2.ng + s3.ng;
        cvt_all_kernel<<<2048, 512>>>(s0, s1, s2, s3, total);
    }

    // one fused persistent kernel for all three GEMMs
    fused3_kernel<<<nsm, NTHR, SMEM_TOTAL>>>(b1, bih, bhh, b3, out);

    (void)in_sizes; (void)n_in; (void)out_size;
}

// round 12
// speedup vs baseline: 1.8779x; 1.8779x over previous
#include <cuda_runtime.h>
#include <cuda_fp16.h>
#include <cstdint>

// ----------------------------------------------------------------------------
// R11: fused persistent 3-GEMM kernel at 256 threads (8 warps), producer
// inlined on tid0 exactly like R7 (no 9th warp -> no register starvation).
//   h = relu(x @ W_init^T + b_init)        tiles 0..2047    (KT=16, 8 n-tiles)
//   o = relu(h @ W_ih^T  + b_ih + b_hh)    tiles 2048..4095 (KT=32, 8 n-tiles)
//   y =       o @ W_final^T + b_final      tiles 4096..5119 (KT=32, 4 n-tiles)
// Deadlock-free: prefetch (3 K-iters < 1 tile) vs cross-phase dependency slack
// (~13 tiles); a spinning CTA has always published everything behind it.
// ----------------------------------------------------------------------------

#define DINLINE __device__ __forceinline__

static constexpr int DIN  = 1024;
static constexpr int DH   = 2048;
static constexpr int DACT = 1024;
static constexpr long MTOK = 32768;

static constexpr int BM = 128;
static constexpr int BN = 256;
static constexpr int BK = 64;            // 128B rows
static constexpr int STAGES = 4;
static constexpr int NTHR = 256;

static constexpr int A_ST = BM * BK * 2;         // 16384 B
static constexpr int B_ST = BN * BK * 2;         // 32768 B
static constexpr int STG  = A_ST + B_ST;         // 49152 B
static constexpr int HDR  = 1024;
static constexpr int SMEM_TOTAL = HDR + STAGES * STG;   // 197632

static constexpr int T1 = 2048;
static constexpr int T2 = 2048;
static constexpr int T3 = 1024;
static constexpr int TTOT = T1 + T2 + T3;   // 5120

DINLINE uint32_t smem_u32(const void* p) {
    uint32_t a;
    asm("{ .reg .u64 t; cvta.to.shared.u64 t, %1; cvt.u32.u64 %0, t; }"
        : "=r"(a) : "l"(p));
    return a;
}

#define MBARRIER_INIT(addr, cnt) \
    asm volatile("mbarrier.init.shared.b64 [%0], %1;" :: "r"(addr), "r"(cnt) : "memory")
#define MBARRIER_ARRIVE(addr) \
    asm volatile("mbarrier.arrive.shared.b64 _, [%0];" :: "r"(addr) : "memory")
#define MBARRIER_EXPECT_TX(addr, n) \
    asm volatile("mbarrier.arrive.expect_tx.shared.b64 _, [%0], %1;" :: "r"(addr), "r"(n) : "memory")

#define MBARRIER_WAIT_PARITY(mbar_smem_addr, phase_parity) do { \
    uint32_t _mbar = (uint32_t)(mbar_smem_addr); \
    uint32_t _parity = (uint32_t)(phase_parity); \
    uint32_t _done; \
    asm volatile( \
        "{\n\t" \
        ".reg .pred p;\n\t" \
        "mbarrier.try_wait.parity.shared.b64 p, [%1], %2;\n\t" \
        "selp.b32 %0, 1, 0, p;\n\t" \
        "}" \
        : "=r"(_done) : "r"(_mbar), "r"(_parity) : "memory"); \
    if (!_done) { \
        asm volatile( \
            "{\n\t" \
            ".reg .pred P1;\n\t" \
            "WAIT_LOOP_%=:\n\t" \
            "mbarrier.try_wait.parity.shared.b64 P1, [%0], %1, 0x989680;\n\t" \
            "@P1 bra.uni WAIT_DONE_%=;\n\t" \
            "bra.uni WAIT_LOOP_%=;\n\t" \
            "WAIT_DONE_%=:\n\t" \
            "}" \
            :: "r"(_mbar), "r"(_parity) : "memory"); \
    } \
} while(0)

#define BULK_G2S(dst, src, sz, mbar) \
    asm volatile("cp.async.bulk.shared::cta.global.mbarrier::complete_tx::bytes [%0], [%1], %2, [%3];" \
        :: "r"((uint32_t)(dst)), "l"(src), "r"((uint32_t)(sz)), "r"((uint32_t)(mbar)) : "memory")

DINLINE void ldsm_x4(uint32_t* r, uint32_t addr) {
    asm volatile("ldmatrix.sync.aligned.m8n8.x4.shared.b16 {%0,%1,%2,%3}, [%4];"
        : "=r"(r[0]), "=r"(r[1]), "=r"(r[2]), "=r"(r[3]) : "r"(addr));
}

DINLINE void mma_f16(float* c, const uint32_t* a, const uint32_t* b) {
    asm volatile(
        "mma.sync.aligned.m16n8k16.row.col.f32.f16.f16.f32 "
        "{%0,%1,%2,%3}, {%4,%5,%6,%7}, {%8,%9}, {%0,%1,%2,%3};"
        : "+f"(c[0]), "+f"(c[1]), "+f"(c[2]), "+f"(c[3])
        : "r"(a[0]), "r"(a[1]), "r"(a[2]), "r"(a[3]), "r"(b[0]), "r"(b[1]));
}

// ----------------------------------------------------------------------------
// Scratch + dependency counters (static device allocations -- allowed).
// ----------------------------------------------------------------------------
__device__ __half g_x [MTOK * DIN];
__device__ __half g_h [MTOK * DH];
__device__ __half g_o [MTOK * DH];
__device__ __half g_w1[(long)DH * DIN];
__device__ __half g_w2[(long)DH * DH];
__device__ __half g_w3[(long)DACT * DH];
__device__ int g_c1[256];   // h m-block ready counters (target 64)
__device__ int g_c2[256];   // o m-block ready counters (target 64)

// ----------------------------------------------------------------------------
// Fused fp32 -> fp16 + tile/swizzle pre-pass (all four tensors, one launch).
// ----------------------------------------------------------------------------
struct CvtSeg {
    const float* in;
    __half* out;
    int ng;
    int kshift;    // log2(K/8)
    int rplog;     // log2(RP)
};

__global__ void __launch_bounds__(512, 2)
cvt_all_kernel(CvtSeg s0, CvtSeg s1, CvtSeg s2, CvtSeg s3, int total)
{
    for (int gi0 = blockIdx.x * blockDim.x + threadIdx.x; gi0 < total;
         gi0 += gridDim.x * blockDim.x) {
        CvtSeg s; int gi = gi0;
        if (gi < s0.ng) s = s0;
        else {
            gi -= s0.ng;
            if (gi < s1.ng) s = s1;
            else {
                gi -= s1.ng;
                if (gi < s2.ng) s = s2;
                else { gi -= s2.ng; s = s3; }
            }
        }
        const int gperrow = 1 << s.kshift;
        const int c8 = gi & (gperrow - 1);
        const int r  = gi >> s.kshift;
        const float4* f4 = reinterpret_cast<const float4*>(s.in);
        float4 v0 = f4[2 * (size_t)gi], v1 = f4[2 * (size_t)gi + 1];
        __half2 h0 = __floats2half2_rn(v0.x, v0.y), h1 = __floats2half2_rn(v0.z, v0.w);
        __half2 h2 = __floats2half2_rn(v1.x, v1.y), h3 = __floats2half2_rn(v1.z, v1.w);
        uint4 o = make_uint4(*reinterpret_cast<uint32_t*>(&h0), *reinterpret_cast<uint32_t*>(&h1),
                             *reinterpret_cast<uint32_t*>(&h2), *reinterpret_cast<uint32_t*>(&h3));
        const int rp = 1 << s.rplog;
        const size_t panel = (size_t)(r >> s.rplog) * (gperrow >> 3) + (c8 >> 3);
        const size_t gip   = (size_t)(r & (rp - 1)) * 8 + ((c8 & 7) ^ (r & 7));
        reinterpret_cast<uint4*>(s.out)[panel * ((size_t)rp * 8) + gip] = o;
    }
}

// tile id -> phase/operands/geometry
DINLINE void decode_tile(int t, const __half*& A, const __half*& B,
                         int& KT, int& ntlog, int& mt, int& nt, int& ph)
{
    int local;
    if (t < T1)            { ph = 1; local = t;           KT = 16; ntlog = 3; A = g_x; B = g_w1; }
    else if (t < T1 + T2)  { ph = 2; local = t - T1;      KT = 32; ntlog = 3; A = g_h; B = g_w2; }
    else                   { ph = 3; local = t - T1 - T2; KT = 32; ntlog = 2; A = g_o; B = g_w3; }
    mt = local >> ntlog;
    nt = local & ((1 << ntlog) - 1);
}

// ----------------------------------------------------------------------------
// Fused persistent 3-GEMM kernel, 256 threads, inline producer on tid0.
// ----------------------------------------------------------------------------
__global__ void __launch_bounds__(NTHR, 1)
fused3_kernel(const float* __restrict__ b1, const float* __restrict__ bih,
              const float* __restrict__ bhh, const float* __restrict__ b3,
              float* __restrict__ out)
{
    extern __shared__ char smem[];
    const uint32_t sbase = smem_u32(smem);
    const int tid = threadIdx.x;
    const int wid = tid >> 5;
    const int lid = tid & 31;
    const int bid = blockIdx.x;
    const int grid = gridDim.x;

    if (tid == 0) {
        #pragma unroll
        for (int s = 0; s < STAGES; ++s) {
            MBARRIER_INIT(sbase + 8 * s, 1);
            MBARRIER_INIT(sbase + 64 + 8 * s, 8);
        }
    }
    __syncthreads();

    const int nMy = (TTOT - bid - 1) / grid + 1;

    // ---- producer cursor state (used by tid0 only) -------------------------
    const __half *pA = nullptr, *pB = nullptr;
    int p_tl = -1, p_kt = 0, p_KT = 0, p_ntlog = 0, p_mt = 0, p_nt = 0, p_ph = 0;
    long pIssued = 0;
    bool pDone = false;

    auto issueNext = [&]() {
        if (pDone) return;
        if (p_kt == p_KT) {
            if (p_tl + 1 >= nMy) { pDone = true; return; }
            ++p_tl;
            decode_tile(bid + p_tl * grid, pA, pB, p_KT, p_ntlog, p_mt, p_nt, p_ph);
            // cross-phase dataflow dependency (slack ~13 tiles; see header)
            if (p_ph == 2)      { while (*(volatile int*)&g_c1[p_mt] < 64) {} }
            else if (p_ph == 3) { while (*(volatile int*)&g_c2[p_mt] < 64) {} }
            if (p_ph != 1) __threadfence();
            p_kt = 0;
        }
        const int s2 = (int)(pIssued & 3);
        if (pIssued >= STAGES)
            MBARRIER_WAIT_PARITY(sbase + 64 + 8 * s2, (uint32_t)(((pIssued >> 2) - 1) & 1));
        const __half* pa = pA + ((size_t)p_mt * p_KT + p_kt) * (A_ST / 2);
        const __half* pb = pB + ((size_t)p_nt * p_KT + p_kt) * (B_ST / 2);
        const uint32_t st = sbase + HDR + s2 * STG;
        MBARRIER_EXPECT_TX(sbase + 8 * s2, STG);
        BULK_G2S(st,        pa, A_ST, sbase + 8 * s2);
        BULK_G2S(st + A_ST, pb, B_ST, sbase + 8 * s2);
        ++p_kt; ++pIssued;
    };

    // prologue: fill first STAGES-1 stages
    if (tid == 0) {
        #pragma unroll
        for (int s = 0; s < STAGES - 1; ++s) issueNext();
    }

    // ---- compute setup -----------------------------------------------------
    const int g   = lid >> 2;
    const int tg  = lid & 3;
    const int warpM = wid >> 2;
    const int warpN = wid & 3;

    const int lm   = lid >> 3;
    const int aRow = warpM * 64 + ((lm & 1) << 3) + (lid & 7);
    const int asel = lm >> 1;
    const int aXor = aRow & 7;
    const int bRow = warpN * 64 + ((lm >> 1) << 3) + (lid & 7);
    const int bsel = lm & 1;
    const int bXor = bRow & 7;
    uint32_t aBase[4], bBase[4];
    #pragma unroll
    for (int i = 0; i < 4; ++i) aBase[i] = (uint32_t)(aRow + i * 16) * 128;
    #pragma unroll
    for (int jp = 0; jp < 4; ++jp) bBase[jp] = (uint32_t)(bRow + jp * 16) * 128;

    long gi = 0;
    for (int tl = 0; tl < nMy; ++tl) {
        const __half *A, *B; int KT, ntlog, mt, nt, ph;
        decode_tile(bid + tl * grid, A, B, KT, ntlog, mt, nt, ph);
        const long m0 = (long)mt * BM;
        const int  n0 = nt * BN;

        float acc[4][8][4];
        #pragma unroll
        for (int i = 0; i < 4; ++i)
            #pragma unroll
            for (int j = 0; j < 8; ++j)
                #pragma unroll
                for (int e = 0; e < 4; ++e) acc[i][j][e] = 0.0f;

        for (int kt = 0; kt < KT; ++kt, ++gi) {
            const int s = (int)(gi & 3);
            MBARRIER_WAIT_PARITY(sbase + 8 * s, (uint32_t)((gi >> 2) & 1));

            const uint32_t sA = sbase + HDR + s * STG;
            const uint32_t sB = sA + A_ST;

            // double-buffered fragments (R7 mainloop, verbatim)
            uint32_t fa[2][4][4], fb[2][4][4];
            {
                const uint32_t aoff = (uint32_t)(((0 + asel) ^ aXor) << 4);
                const uint32_t boff = (uint32_t)(((0 + bsel) ^ bXor) << 4);
                #pragma unroll
                for (int i = 0; i < 4; ++i)    ldsm_x4(fa[0][i],  sA + aBase[i]  + aoff);
                #pragma unroll
                for (int jp = 0; jp < 4; ++jp) ldsm_x4(fb[0][jp], sB + bBase[jp] + boff);
            }
            #pragma unroll
            for (int kk = 0; kk < 4; ++kk) {
                const int cur = kk & 1, nxt = cur ^ 1;
                if (kk < 3) {
                    const uint32_t aoff = (uint32_t)((((kk + 1) * 2 + asel) ^ aXor) << 4);
                    const uint32_t boff = (uint32_t)((((kk + 1) * 2 + bsel) ^ bXor) << 4);
                    #pragma unroll
                    for (int i = 0; i < 4; ++i)    ldsm_x4(fa[nxt][i],  sA + aBase[i]  + aoff);
                    #pragma unroll
                    for (int jp = 0; jp < 4; ++jp) ldsm_x4(fb[nxt][jp], sB + bBase[jp] + boff);
                }
                #pragma unroll
                for (int i = 0; i < 4; ++i)
                    #pragma unroll
                    for (int j = 0; j < 8; ++j)
                        mma_f16(acc[i][j], fa[cur][i], &fb[cur][j >> 1][(j & 1) * 2]);
            }

            __syncwarp();
            if (lid == 0) MBARRIER_ARRIVE(sbase + 64 + 8 * s);

            // producer AFTER compute (R7 placement): issue next prefetch
            if (tid == 0) issueNext();
        }

        // ---- epilogue (phase-dependent) ------------------------------------
        const float* bias1 = (ph == 1) ? b1 : (ph == 2) ? bih : b3;
        const float* bias2 = (ph == 2) ? bhh : nullptr;
        const int N = (ph == 3) ? DACT : DH;
        const int jb0 = n0 + warpN * 64;

        #pragma unroll
        for (int j = 0; j < 8; ++j) {
            const int col = jb0 + j * 8 + 2 * tg;
            float bb0 = bias1[col], bb1 = bias1[col + 1];
            if (bias2) { bb0 += bias2[col]; bb1 += bias2[col + 1]; }
            #pragma unroll
            for (int i = 0; i < 4; ++i) {
                const long r0 = m0 + warpM * 64 + i * 16 + g;
                #pragma unroll
                for (int h = 0; h < 2; ++h) {
                    const long r = r0 + 8 * h;
                    float v0 = acc[i][j][2 * h + 0] + bb0;
                    float v1 = acc[i][j][2 * h + 1] + bb1;
                    if (ph != 3) {
                        v0 = fmaxf(v0, 0.0f); v1 = fmaxf(v1, 0.0f);
                        __half2 hv = __floats2half2_rn(v0, v1);
                        __half* Cp = (ph == 1) ? g_h : g_o;
                        const size_t panel = ((size_t)(r >> 7) * (N >> 6) + (col >> 6)) << 13;
                        const size_t off = panel + (size_t)((int)(r & 127)) * 64
                                         + (size_t)(((((col >> 3) & 7) ^ ((int)r & 7)) << 3) + (col & 7));
                        *reinterpret_cast<uint32_t*>(Cp + off) =
                            *reinterpret_cast<uint32_t*>(&hv);
                    } else {
                        *reinterpret_cast<float2*>(out + (size_t)r * N + col) =
                            make_float2(v0, v1);
                    }
                }
            }
        }

        // publish this tile's slice of the m-block
        if (ph != 3) {
            __threadfence();
            __syncwarp();
            if (lid == 0) {
                if (ph == 1) atomicAdd(&g_c1[mt], 1);
                else         atomicAdd(&g_c2[mt], 1);
            }
        }
    }
}

// ----------------------------------------------------------------------------
// Host launcher
// ----------------------------------------------------------------------------
extern "C" void kernel_launch(void* const* d_in, const int* in_sizes, int n_in,
                              void* d_out, int out_size)
{
    const float* x    = (const float*)d_in[0];
    const float* W1   = (const float*)d_in[1];
    const float* b1   = (const float*)d_in[2];
    const float* W2   = (const float*)d_in[3];
    const float* bih  = (const float*)d_in[4];
    const float* bhh  = (const float*)d_in[5];
    const float* W3   = (const float*)d_in[6];
    const float* b3   = (const float*)d_in[7];
    float* out = (float*)d_out;

    __half *gx, *gw1, *gw2, *gw3;
    cudaGetSymbolAddress((void**)&gx,  g_x);
    cudaGetSymbolAddress((void**)&gw1, g_w1);
    cudaGetSymbolAddress((void**)&gw2, g_w2);
    cudaGetSymbolAddress((void**)&gw3, g_w3);

    int *c1, *c2;
    cudaGetSymbolAddress((void**)&c1, g_c1);
    cudaGetSymbolAddress((void**)&c2, g_c2);
    cudaMemsetAsync(c1, 0, 256 * sizeof(int));
    cudaMemsetAsync(c2, 0, 256 * sizeof(int));

    cudaFuncSetAttribute(fused3_kernel,
                         cudaFuncAttributeMaxDynamicSharedMemorySize, SMEM_TOTAL);

    int nsm = 148;
    cudaDeviceGetAttribute(&nsm, cudaDevAttrMultiProcessorCount, 0);

    // fused pre-pass: fp32 -> fp16 into swizzled panels (single launch)
    {
        CvtSeg s0 = { x,  gx,  (int)(MTOK * (long)DIN / 8), 7, 7 };   // RP=128
        CvtSeg s1 = { W1, gw1, (int)((long)DH * DIN / 8),   7, 8 };   // RP=256
        CvtSeg s2 = { W2, gw2, (int)((long)DH * DH / 8),    8, 8 };
        CvtSeg s3 = { W3, gw3, (int)((long)DACT * DH / 8),  8, 8 };
        const int total = s0.ng + s1.ng + s2.ng + s3.ng;
        cvt_all_kernel<<<2048, 512>>>(s0, s1, s2, s3, total);
    }

    // one fused persistent kernel for all three GEMMs
    fused3_kernel<<<nsm, NTHR, SMEM_TOTAL>>>(b1, bih, bhh, b3, out);

    (void)in_sizes; (void)n_in; (void)out_size;
}

// round 13
// speedup vs baseline: 1.9223x; 1.0236x over previous
#include <cuda_runtime.h>
#include <cuda_fp16.h>
#include <cstdint>

// ----------------------------------------------------------------------------
// R12 = R7 (best: 1120us) + selective kk3-hoist: the stage-boundary wait is
// hoisted under queued MMAs ONLY in the fp32 GEMM3 instantiation (where R8
// measured 277.4 -> 270.6us); GEMM1/2 keep R7's exact loop and register count.
//
//   h = relu(x @ W_init^T + b_init)        M=32768 N=2048 K=1024
//   o = relu(h @ W_ih^T  + b_ih + b_hh)    M=32768 N=2048 K=2048
//   y =       o @ W_final^T + b_final      M=32768 N=1024 K=2048
//
// fp16 mma.sync m16n8k16 + ldmatrix, cp.async.bulk + mbarrier pipeline,
// persistent CTAs, CTA tile 128x256, BK=64, 4 stages, 8 warps.
// ----------------------------------------------------------------------------

#define DINLINE __device__ __forceinline__

static constexpr int DIN  = 1024;
static constexpr int DH   = 2048;
static constexpr int DACT = 1024;
static constexpr long MTOK = 32768;

static constexpr int BM = 128;
static constexpr int BN = 256;
static constexpr int BK = 64;            // 128B rows
static constexpr int STAGES = 4;
static constexpr int NTHR = 256;

static constexpr int A_ST = BM * BK * 2;         // 16384 B
static constexpr int B_ST = BN * BK * 2;         // 32768 B
static constexpr int STG  = A_ST + B_ST;         // 49152 B
static constexpr int HDR  = 1024;
static constexpr int SMEM_TOTAL = HDR + STAGES * STG;   // 197632

DINLINE uint32_t smem_u32(const void* p) {
    uint32_t a;
    asm("{ .reg .u64 t; cvta.to.shared.u64 t, %1; cvt.u32.u64 %0, t; }"
        : "=r"(a) : "l"(p));
    return a;
}

#define MBARRIER_INIT(addr, cnt) \
    asm volatile("mbarrier.init.shared.b64 [%0], %1;" :: "r"(addr), "r"(cnt) : "memory")
#define MBARRIER_ARRIVE(addr) \
    asm volatile("mbarrier.arrive.shared.b64 _, [%0];" :: "r"(addr) : "memory")
#define MBARRIER_EXPECT_TX(addr, n) \
    asm volatile("mbarrier.arrive.expect_tx.shared.b64 _, [%0], %1;" :: "r"(addr), "r"(n) : "memory")

#define MBARRIER_WAIT_PARITY(mbar_smem_addr, phase_parity) do { \
    uint32_t _mbar = (uint32_t)(mbar_smem_addr); \
    uint32_t _parity = (uint32_t)(phase_parity); \
    uint32_t _done; \
    asm volatile( \
        "{\n\t" \
        ".reg .pred p;\n\t" \
        "mbarrier.try_wait.parity.shared.b64 p, [%1], %2;\n\t" \
        "selp.b32 %0, 1, 0, p;\n\t" \
        "}" \
        : "=r"(_done) : "r"(_mbar), "r"(_parity) : "memory"); \
    if (!_done) { \
        asm volatile( \
            "{\n\t" \
            ".reg .pred P1;\n\t" \
            "WAIT_LOOP_%=:\n\t" \
            "mbarrier.try_wait.parity.shared.b64 P1, [%0], %1, 0x989680;\n\t" \
            "@P1 bra.uni WAIT_DONE_%=;\n\t" \
            "bra.uni WAIT_LOOP_%=;\n\t" \
            "WAIT_DONE_%=:\n\t" \
            "}" \
            :: "r"(_mbar), "r"(_parity) : "memory"); \
    } \
} while(0)

#define BULK_G2S(dst, src, sz, mbar) \
    asm volatile("cp.async.bulk.shared::cta.global.mbarrier::complete_tx::bytes [%0], [%1], %2, [%3];" \
        :: "r"((uint32_t)(dst)), "l"(src), "r"((uint32_t)(sz)), "r"((uint32_t)(mbar)) : "memory")

DINLINE void ldsm_x4(uint32_t* r, uint32_t addr) {
    asm volatile("ldmatrix.sync.aligned.m8n8.x4.shared.b16 {%0,%1,%2,%3}, [%4];"
        : "=r"(r[0]), "=r"(r[1]), "=r"(r[2]), "=r"(r[3]) : "r"(addr));
}

DINLINE void mma_f16(float* c, const uint32_t* a, const uint32_t* b) {
    asm volatile(
        "mma.sync.aligned.m16n8k16.row.col.f32.f16.f16.f32 "
        "{%0,%1,%2,%3}, {%4,%5,%6,%7}, {%8,%9}, {%0,%1,%2,%3};"
        : "+f"(c[0]), "+f"(c[1]), "+f"(c[2]), "+f"(c[3])
        : "r"(a[0]), "r"(a[1]), "r"(a[2]), "r"(a[3]), "r"(b[0]), "r"(b[1]));
}

// ----------------------------------------------------------------------------
// Scratch (static device allocations -- allowed). All in swizzled panel layout.
// ----------------------------------------------------------------------------
__device__ __half g_x [MTOK * DIN];
__device__ __half g_h [MTOK * DH];
__device__ __half g_o [MTOK * DH];
__device__ __half g_w1[(long)DH * DIN];
__device__ __half g_w2[(long)DH * DH];
__device__ __half g_w3[(long)DACT * DH];

// ----------------------------------------------------------------------------
// Fused fp32 -> fp16 + tile/swizzle pre-pass (all four tensors, one launch).
// ----------------------------------------------------------------------------
struct CvtSeg {
    const float* in;
    __half* out;
    int ng;        // granule count
    int kshift;    // log2(K/8)
    int rplog;     // log2(RP)
};

__global__ void __launch_bounds__(512, 2)
cvt_all_kernel(CvtSeg s0, CvtSeg s1, CvtSeg s2, CvtSeg s3, int total)
{
    for (int gi0 = blockIdx.x * blockDim.x + threadIdx.x; gi0 < total;
         gi0 += gridDim.x * blockDim.x) {
        CvtSeg s; int gi = gi0;
        if (gi < s0.ng) s = s0;
        else {
            gi -= s0.ng;
            if (gi < s1.ng) s = s1;
            else {
                gi -= s1.ng;
                if (gi < s2.ng) s = s2;
                else { gi -= s2.ng; s = s3; }
            }
        }
        const int gperrow = 1 << s.kshift;
        const int c8 = gi & (gperrow - 1);
        const int r  = gi >> s.kshift;
        const float4* f4 = reinterpret_cast<const float4*>(s.in);
        float4 v0 = f4[2 * (size_t)gi], v1 = f4[2 * (size_t)gi + 1];
        __half2 h0 = __floats2half2_rn(v0.x, v0.y), h1 = __floats2half2_rn(v0.z, v0.w);
        __half2 h2 = __floats2half2_rn(v1.x, v1.y), h3 = __floats2half2_rn(v1.z, v1.w);
        uint4 o = make_uint4(*reinterpret_cast<uint32_t*>(&h0), *reinterpret_cast<uint32_t*>(&h1),
                             *reinterpret_cast<uint32_t*>(&h2), *reinterpret_cast<uint32_t*>(&h3));
        const int rp = 1 << s.rplog;
        const size_t panel = (size_t)(r >> s.rplog) * (gperrow >> 3) + (c8 >> 3);
        const size_t gip   = (size_t)(r & (rp - 1)) * 8 + ((c8 & 7) ^ (r & 7));
        reinterpret_cast<uint4*>(s.out)[panel * ((size_t)rp * 8) + gip] = o;
    }
}

// ----------------------------------------------------------------------------
// Persistent GEMM: C = act(A @ B^T + bias1 (+bias2)); A,B in swizzled panels.
// HOIST: stage-wait hoisted under queued MMAs (GEMM3 / fp32-out only).
// ----------------------------------------------------------------------------
template <bool HALF_OUT, bool RELU, bool HOIST>
__global__ void __launch_bounds__(NTHR, 1)
gemm_f16_kernel(const __half* __restrict__ A, const __half* __restrict__ Bw,
                void* __restrict__ Cv,
                const float* __restrict__ bias1, const float* __restrict__ bias2,
                int N, int ktlog, int ntlog, int Ttiles)
{
    extern __shared__ char smem[];
    const uint32_t sbase = smem_u32(smem);
    const int tid = threadIdx.x;
    const int wid = tid >> 5;
    const int lid = tid & 31;
    const int g   = lid >> 2;
    const int tg  = lid & 3;
    const int bid = blockIdx.x;
    const int grid = gridDim.x;
    const int KT = 1 << ktlog;
    const int ntmask = (1 << ntlog) - 1;

    const int warpM = wid >> 2;
    const int warpN = wid & 3;

    // mbarriers: full[s] @ 8s, empty[s] @ 64+8s
    if (tid == 0) {
        #pragma unroll
        for (int s = 0; s < STAGES; ++s) {
            MBARRIER_INIT(sbase + 8 * s, 1);
            MBARRIER_INIT(sbase + 64 + 8 * s, 8);
        }
    }
    __syncthreads();

    const int nMy = (bid < Ttiles) ? ((Ttiles - bid - 1) / grid + 1) : 0;
    if (nMy == 0) return;
    const long totIt = (long)nMy << ktlog;

    // map global iteration q -> (A panel, B panel) source pointers
    auto panels = [&](long q, const __half*& pa, const __half*& pb) {
        const int tIdx = (int)(q >> ktlog);
        const int kt   = (int)(q & (KT - 1));
        const int tile = bid + tIdx * grid;
        const int mtq  = tile >> ntlog;
        const int ntq  = tile & ntmask;
        pa = A  + ((size_t)mtq * KT + kt) * (A_ST / 2);
        pb = Bw + ((size_t)ntq * KT + kt) * (B_ST / 2);
    };

    // prologue: fill first min(STAGES-1, totIt) stages
    if (tid == 0) {
        #pragma unroll
        for (int s = 0; s < STAGES - 1; ++s) {
            if (s < totIt) {
                const __half *pa, *pb;
                panels(s, pa, pb);
                const uint32_t st = sbase + HDR + s * STG;
                MBARRIER_EXPECT_TX(sbase + 8 * s, STG);
                BULK_G2S(st,        pa, A_ST, sbase + 8 * s);
                BULK_G2S(st + A_ST, pb, B_ST, sbase + 8 * s);
            }
        }
    }

    // ldmatrix per-lane bases (swizzled granule addressing)
    const int lm   = lid >> 3;
    const int aRow = warpM * 64 + ((lm & 1) << 3) + (lid & 7);
    const int asel = lm >> 1;
    const int aXor = aRow & 7;
    const int bRow = warpN * 64 + ((lm >> 1) << 3) + (lid & 7);
    const int bsel = lm & 1;
    const int bXor = bRow & 7;
    uint32_t aBase[4], bBase[4];
    #pragma unroll
    for (int i = 0; i < 4; ++i) aBase[i] = (uint32_t)(aRow + i * 16) * 128;
    #pragma unroll
    for (int jp = 0; jp < 4; ++jp) bBase[jp] = (uint32_t)(bRow + jp * 16) * 128;

    // HOIST variant: fragment buffer persists across stage/tile boundaries
    uint32_t fa[2][4][4], fb[2][4][4];
    if (HOIST) {
        MBARRIER_WAIT_PARITY(sbase + 0, 0);
        const uint32_t sA0 = sbase + HDR;
        const uint32_t sB0 = sA0 + A_ST;
        const uint32_t aoff = (uint32_t)(((0 + asel) ^ aXor) << 4);
        const uint32_t boff = (uint32_t)(((0 + bsel) ^ bXor) << 4);
        #pragma unroll
        for (int i = 0; i < 4; ++i)    ldsm_x4(fa[0][i],  sA0 + aBase[i]  + aoff);
        #pragma unroll
        for (int jp = 0; jp < 4; ++jp) ldsm_x4(fb[0][jp], sB0 + bBase[jp] + boff);
    }

    for (int tl = 0; tl < nMy; ++tl) {
        const int tile = bid + tl * grid;
        const int mt = tile >> ntlog;
        const int nt = tile & ntmask;
        const long m0 = (long)mt * BM;
        const int  n0 = nt * BN;
        const long gbase = (long)tl << ktlog;

        float acc[4][8][4];
        #pragma unroll
        for (int i = 0; i < 4; ++i)
            #pragma unroll
            for (int j = 0; j < 8; ++j)
                #pragma unroll
                for (int e = 0; e < 4; ++e) acc[i][j][e] = 0.0f;

        for (int kt = 0; kt < KT; ++kt) {
            const long gi = gbase + kt;
            const int s = (int)(gi & (STAGES - 1));
            const uint32_t sA = sbase + HDR + s * STG;
            const uint32_t sB = sA + A_ST;

            if (!HOIST) {
                // ---- R7 loop: wait at stage top, local double-buffer -------
                MBARRIER_WAIT_PARITY(sbase + 8 * s, (uint32_t)((gi >> 2) & 1));
                {
                    const uint32_t aoff = (uint32_t)(((0 + asel) ^ aXor) << 4);
                    const uint32_t boff = (uint32_t)(((0 + bsel) ^ bXor) << 4);
                    #pragma unroll
                    for (int i = 0; i < 4; ++i)    ldsm_x4(fa[0][i],  sA + aBase[i]  + aoff);
                    #pragma unroll
                    for (int jp = 0; jp < 4; ++jp) ldsm_x4(fb[0][jp], sB + bBase[jp] + boff);
                }
                #pragma unroll
                for (int kk = 0; kk < 4; ++kk) {
                    const int cur = kk & 1, nxt = cur ^ 1;
                    if (kk < 3) {
                        const uint32_t aoff = (uint32_t)((((kk + 1) * 2 + asel) ^ aXor) << 4);
                        const uint32_t boff = (uint32_t)((((kk + 1) * 2 + bsel) ^ bXor) << 4);
                        #pragma unroll
                        for (int i = 0; i < 4; ++i)    ldsm_x4(fa[nxt][i],  sA + aBase[i]  + aoff);
                        #pragma unroll
                        for (int jp = 0; jp < 4; ++jp) ldsm_x4(fb[nxt][jp], sB + bBase[jp] + boff);
                    }
                    #pragma unroll
                    for (int i = 0; i < 4; ++i)
                        #pragma unroll
                        for (int j = 0; j < 8; ++j)
                            mma_f16(acc[i][j], fa[cur][i], &fb[cur][j >> 1][(j & 1) * 2]);
                }
                __syncwarp();
                if (lid == 0) MBARRIER_ARRIVE(sbase + 64 + 8 * s);
            } else {
                // ---- R8 loop: next-stage wait hoisted under kk=3's MMAs ----
                #pragma unroll
                for (int kk = 0; kk < 3; ++kk) {
                    const int cur = kk & 1, nxt = cur ^ 1;
                    const uint32_t aoff = (uint32_t)((((kk + 1) * 2 + asel) ^ aXor) << 4);
                    const uint32_t boff = (uint32_t)((((kk + 1) * 2 + bsel) ^ bXor) << 4);
                    #pragma unroll
                    for (int i = 0; i < 4; ++i)    ldsm_x4(fa[nxt][i],  sA + aBase[i]  + aoff);
                    #pragma unroll
                    for (int jp = 0; jp < 4; ++jp) ldsm_x4(fb[nxt][jp], sB + bBase[jp] + boff);
                    #pragma unroll
                    for (int i = 0; i < 4; ++i)
                        #pragma unroll
                        for (int j = 0; j < 8; ++j)
                            mma_f16(acc[i][j], fa[cur][i], &fb[cur][j >> 1][(j & 1) * 2]);
                }
                if (gi + 1 < totIt) {
                    const int sn = (int)((gi + 1) & (STAGES - 1));
                    MBARRIER_WAIT_PARITY(sbase + 8 * sn, (uint32_t)(((gi + 1) >> 2) & 1));
                    const uint32_t sAn = sbase + HDR + sn * STG;
                    const uint32_t sBn = sAn + A_ST;
                    const uint32_t aoff = (uint32_t)(((0 + asel) ^ aXor) << 4);
                    const uint32_t boff = (uint32_t)(((0 + bsel) ^ bXor) << 4);
                    #pragma unroll
                    for (int i = 0; i < 4; ++i)    ldsm_x4(fa[0][i],  sAn + aBase[i]  + aoff);
                    #pragma unroll
                    for (int jp = 0; jp < 4; ++jp) ldsm_x4(fb[0][jp], sBn + bBase[jp] + boff);
                }
                #pragma unroll
                for (int i = 0; i < 4; ++i)
                    #pragma unroll
                    for (int j = 0; j < 8; ++j)
                        mma_f16(acc[i][j], fa[1][i], &fb[1][j >> 1][(j & 1) * 2]);
                __syncwarp();
                if (lid == 0) MBARRIER_ARRIVE(sbase + 64 + 8 * s);
            }

            // producer AFTER compute: refill stage (gi + STAGES-1)
            const long pf = gi + STAGES - 1;
            if (tid == 0 && pf < totIt) {
                const int s2 = (int)(pf & (STAGES - 1));
                if (pf >= STAGES)
                    MBARRIER_WAIT_PARITY(sbase + 64 + 8 * s2, (uint32_t)(((pf >> 2) - 1) & 1));
                const __half *pa, *pb;
                panels(pf, pa, pb);
                const uint32_t st = sbase + HDR + s2 * STG;
                MBARRIER_EXPECT_TX(sbase + 8 * s2, STG);
                BULK_G2S(st,        pa, A_ST, sbase + 8 * s2);
                BULK_G2S(st + A_ST, pb, B_ST, sbase + 8 * s2);
            }
        }

        // ---- epilogue ------------------------------------------------------
        const bool has2 = (bias2 != nullptr);
        const int jb0 = n0 + warpN * 64;

        #pragma unroll
        for (int j = 0; j < 8; ++j) {
            const int col = jb0 + j * 8 + 2 * tg;
            float bb0 = bias1[col], bb1 = bias1[col + 1];
            if (has2) { bb0 += bias2[col]; bb1 += bias2[col + 1]; }
            #pragma unroll
            for (int i = 0; i < 4; ++i) {
                const long r0 = m0 + warpM * 64 + i * 16 + g;
                #pragma unroll
                for (int h = 0; h < 2; ++h) {
                    const long r = r0 + 8 * h;
                    float v0 = acc[i][j][2 * h + 0] + bb0;
                    float v1 = acc[i][j][2 * h + 1] + bb1;
                    if (RELU) { v0 = fmaxf(v0, 0.0f); v1 = fmaxf(v1, 0.0f); }
                    if (HALF_OUT) {
                        // swizzled 128-row panel layout (next GEMM's A operand)
                        __half2 hv = __floats2half2_rn(v0, v1);
                        const size_t panel = ((size_t)(r >> 7) * (N >> 6) + (col >> 6)) << 13;
                        const size_t off = panel + (size_t)((int)(r & 127)) * 64
                                         + (size_t)(((((col >> 3) & 7) ^ ((int)r & 7)) << 3) + (col & 7));
                        *reinterpret_cast<uint32_t*>((__half*)Cv + off) =
                            *reinterpret_cast<uint32_t*>(&hv);
                    } else {
                        *reinterpret_cast<float2*>((float*)Cv + (size_t)r * N + col) =
                            make_float2(v0, v1);
                    }
                }
            }
        }
    }
}

// ----------------------------------------------------------------------------
// Host launcher
// ----------------------------------------------------------------------------
extern "C" void kernel_launch(void* const* d_in, const int* in_sizes, int n_in,
                              void* d_out, int out_size)
{
    const float* x    = (const float*)d_in[0];
    const float* W1   = (const float*)d_in[1];
    const float* b1   = (const float*)d_in[2];
    const float* W2   = (const float*)d_in[3];
    const float* bih  = (const float*)d_in[4];
    const float* bhh  = (const float*)d_in[5];
    const float* W3   = (const float*)d_in[6];
    const float* b3   = (const float*)d_in[7];
    float* out = (float*)d_out;

    __half *gx, *gh, *go, *gw1, *gw2, *gw3;
    cudaGetSymbolAddress((void**)&gx,  g_x);
    cudaGetSymbolAddress((void**)&gh,  g_h);
    cudaGetSymbolAddress((void**)&go,  g_o);
    cudaGetSymbolAddress((void**)&gw1, g_w1);
    cudaGetSymbolAddress((void**)&gw2, g_w2);
    cudaGetSymbolAddress((void**)&gw3, g_w3);

    cudaFuncSetAttribute(gemm_f16_kernel<true, true, false>,
                         cudaFuncAttributeMaxDynamicSharedMemorySize, SMEM_TOTAL);
    cudaFuncSetAttribute(gemm_f16_kernel<false, false, true>,
                         cudaFuncAttributeMaxDynamicSharedMemorySize, SMEM_TOTAL);

    int nsm = 148;
    cudaDeviceGetAttribute(&nsm, cudaDevAttrMultiProcessorCount, 0);

    // fused pre-pass: fp32 -> fp16 into swizzled panels (single launch)
    {
        CvtSeg s0 = { x,  gx,  (int)(MTOK * (long)DIN / 8), 7, 7 };   // RP=128
        CvtSeg s1 = { W1, gw1, (int)((long)DH * DIN / 8),   7, 8 };   // RP=256
        CvtSeg s2 = { W2, gw2, (int)((long)DH * DH / 8),    8, 8 };
        CvtSeg s3 = { W3, gw3, (int)((long)DACT * DH / 8),  8, 8 };
        const int total = s0.ng + s1.ng + s2.ng + s3.ng;
        cvt_all_kernel<<<2048, 512>>>(s0, s1, s2, s3, total);
    }

    const int Mtiles = (int)(MTOK / BM);   // 256

    // GEMM1: h = relu(x @ W1^T + b1) -> fp16 panels   (KT=16, ktlog=4, ntlog=3)
    gemm_f16_kernel<true, true, false><<<nsm, NTHR, SMEM_TOTAL>>>(
        gx, gw1, gh, b1, nullptr, DH, 4, 3, Mtiles * (DH / BN));

    // GEMM2: o = relu(h @ W2^T + bih + bhh) -> fp16 panels (KT=32, ktlog=5, ntlog=3)
    gemm_f16_kernel<true, true, false><<<nsm, NTHR, SMEM_TOTAL>>>(
        gh, gw2, go, bih, bhh, DH, 5, 3, Mtiles * (DH / BN));

    // GEMM3: y = o @ W3^T + b3 -> fp32 row-major      (KT=32, ktlog=5, ntlog=2, HOIST)
    gemm_f16_kernel<false, false, true><<<nsm, NTHR, SMEM_TOTAL>>>(
        go, gw3, out, b3, nullptr, DACT, 5, 2, Mtiles * (DACT / BN));

    (void)in_sizes; (void)n_in; (void)out_size;
}

// round 14
// speedup vs baseline: 1.9736x; 1.0267x over previous
#include <cuda_runtime.h>
#include <cuda_fp16.h>
#include <cstdint>

// ----------------------------------------------------------------------------
// R13: two SEPARATE kernels (no shared template -> no register coupling):
//   gemm_f16_kernel       = R7 body verbatim  (GEMM1, GEMM2; fp16 panel out)
//   gemm_f16_hoist_kernel = R8 body           (GEMM3 only; fp32 out, stage-wait
//                                              hoisted under queued MMAs)
//
//   h = relu(x @ W_init^T + b_init)        M=32768 N=2048 K=1024
//   o = relu(h @ W_ih^T  + b_ih + b_hh)    M=32768 N=2048 K=2048
//   y =       o @ W_final^T + b_final      M=32768 N=1024 K=2048
//
// fp16 mma.sync m16n8k16 + ldmatrix, cp.async.bulk + mbarrier pipeline,
// persistent CTAs, CTA tile 128x256, BK=64, 4 stages, 8 warps.
// ----------------------------------------------------------------------------

#define DINLINE __device__ __forceinline__

static constexpr int DIN  = 1024;
static constexpr int DH   = 2048;
static constexpr int DACT = 1024;
static constexpr long MTOK = 32768;

static constexpr int BM = 128;
static constexpr int BN = 256;
static constexpr int BK = 64;            // 128B rows
static constexpr int STAGES = 4;
static constexpr int NTHR = 256;

static constexpr int A_ST = BM * BK * 2;         // 16384 B
static constexpr int B_ST = BN * BK * 2;         // 32768 B
static constexpr int STG  = A_ST + B_ST;         // 49152 B
static constexpr int HDR  = 1024;
static constexpr int SMEM_TOTAL = HDR + STAGES * STG;   // 197632

DINLINE uint32_t smem_u32(const void* p) {
    uint32_t a;
    asm("{ .reg .u64 t; cvta.to.shared.u64 t, %1; cvt.u32.u64 %0, t; }"
        : "=r"(a) : "l"(p));
    return a;
}

#define MBARRIER_INIT(addr, cnt) \
    asm volatile("mbarrier.init.shared.b64 [%0], %1;" :: "r"(addr), "r"(cnt) : "memory")
#define MBARRIER_ARRIVE(addr) \
    asm volatile("mbarrier.arrive.shared.b64 _, [%0];" :: "r"(addr) : "memory")
#define MBARRIER_EXPECT_TX(addr, n) \
    asm volatile("mbarrier.arrive.expect_tx.shared.b64 _, [%0], %1;" :: "r"(addr), "r"(n) : "memory")

#define MBARRIER_WAIT_PARITY(mbar_smem_addr, phase_parity) do { \
    uint32_t _mbar = (uint32_t)(mbar_smem_addr); \
    uint32_t _parity = (uint32_t)(phase_parity); \
    uint32_t _done; \
    asm volatile( \
        "{\n\t" \
        ".reg .pred p;\n\t" \
        "mbarrier.try_wait.parity.shared.b64 p, [%1], %2;\n\t" \
        "selp.b32 %0, 1, 0, p;\n\t" \
        "}" \
        : "=r"(_done) : "r"(_mbar), "r"(_parity) : "memory"); \
    if (!_done) { \
        asm volatile( \
            "{\n\t" \
            ".reg .pred P1;\n\t" \
            "WAIT_LOOP_%=:\n\t" \
            "mbarrier.try_wait.parity.shared.b64 P1, [%0], %1, 0x989680;\n\t" \
            "@P1 bra.uni WAIT_DONE_%=;\n\t" \
            "bra.uni WAIT_LOOP_%=;\n\t" \
            "WAIT_DONE_%=:\n\t" \
            "}" \
            :: "r"(_mbar), "r"(_parity) : "memory"); \
    } \
} while(0)

#define BULK_G2S(dst, src, sz, mbar) \
    asm volatile("cp.async.bulk.shared::cta.global.mbarrier::complete_tx::bytes [%0], [%1], %2, [%3];" \
        :: "r"((uint32_t)(dst)), "l"(src), "r"((uint32_t)(sz)), "r"((uint32_t)(mbar)) : "memory")

DINLINE void ldsm_x4(uint32_t* r, uint32_t addr) {
    asm volatile("ldmatrix.sync.aligned.m8n8.x4.shared.b16 {%0,%1,%2,%3}, [%4];"
        : "=r"(r[0]), "=r"(r[1]), "=r"(r[2]), "=r"(r[3]) : "r"(addr));
}

DINLINE void mma_f16(float* c, const uint32_t* a, const uint32_t* b) {
    asm volatile(
        "mma.sync.aligned.m16n8k16.row.col.f32.f16.f16.f32 "
        "{%0,%1,%2,%3}, {%4,%5,%6,%7}, {%8,%9}, {%0,%1,%2,%3};"
        : "+f"(c[0]), "+f"(c[1]), "+f"(c[2]), "+f"(c[3])
        : "r"(a[0]), "r"(a[1]), "r"(a[2]), "r"(a[3]), "r"(b[0]), "r"(b[1]));
}

// ----------------------------------------------------------------------------
// Scratch (static device allocations -- allowed). All in swizzled panel layout.
// ----------------------------------------------------------------------------
__device__ __half g_x [MTOK * DIN];
__device__ __half g_h [MTOK * DH];
__device__ __half g_o [MTOK * DH];
__device__ __half g_w1[(long)DH * DIN];
__device__ __half g_w2[(long)DH * DH];
__device__ __half g_w3[(long)DACT * DH];

// ----------------------------------------------------------------------------
// Fused fp32 -> fp16 + tile/swizzle pre-pass (all four tensors, one launch).
// ----------------------------------------------------------------------------
struct CvtSeg {
    const float* in;
    __half* out;
    int ng;        // granule count
    int kshift;    // log2(K/8)
    int rplog;     // log2(RP)
};

__global__ void __launch_bounds__(512, 2)
cvt_all_kernel(CvtSeg s0, CvtSeg s1, CvtSeg s2, CvtSeg s3, int total)
{
    for (int gi0 = blockIdx.x * blockDim.x + threadIdx.x; gi0 < total;
         gi0 += gridDim.x * blockDim.x) {
        CvtSeg s; int gi = gi0;
        if (gi < s0.ng) s = s0;
        else {
            gi -= s0.ng;
            if (gi < s1.ng) s = s1;
            else {
                gi -= s1.ng;
                if (gi < s2.ng) s = s2;
                else { gi -= s2.ng; s = s3; }
            }
        }
        const int gperrow = 1 << s.kshift;
        const int c8 = gi & (gperrow - 1);
        const int r  = gi >> s.kshift;
        const float4* f4 = reinterpret_cast<const float4*>(s.in);
        float4 v0 = f4[2 * (size_t)gi], v1 = f4[2 * (size_t)gi + 1];
        __half2 h0 = __floats2half2_rn(v0.x, v0.y), h1 = __floats2half2_rn(v0.z, v0.w);
        __half2 h2 = __floats2half2_rn(v1.x, v1.y), h3 = __floats2half2_rn(v1.z, v1.w);
        uint4 o = make_uint4(*reinterpret_cast<uint32_t*>(&h0), *reinterpret_cast<uint32_t*>(&h1),
                             *reinterpret_cast<uint32_t*>(&h2), *reinterpret_cast<uint32_t*>(&h3));
        const int rp = 1 << s.rplog;
        const size_t panel = (size_t)(r >> s.rplog) * (gperrow >> 3) + (c8 >> 3);
        const size_t gip   = (size_t)(r & (rp - 1)) * 8 + ((c8 & 7) ^ (r & 7));
        reinterpret_cast<uint4*>(s.out)[panel * ((size_t)rp * 8) + gip] = o;
    }
}

// ----------------------------------------------------------------------------
// Kernel A (R7 verbatim): persistent GEMM, fp16 panel out + relu.
// ----------------------------------------------------------------------------
template <bool HALF_OUT, bool RELU>
__global__ void __launch_bounds__(NTHR, 1)
gemm_f16_kernel(const __half* __restrict__ A, const __half* __restrict__ Bw,
                void* __restrict__ Cv,
                const float* __restrict__ bias1, const float* __restrict__ bias2,
                int N, int ktlog, int ntlog, int Ttiles)
{
    extern __shared__ char smem[];
    const uint32_t sbase = smem_u32(smem);
    const int tid = threadIdx.x;
    const int wid = tid >> 5;
    const int lid = tid & 31;
    const int g   = lid >> 2;
    const int tg  = lid & 3;
    const int bid = blockIdx.x;
    const int grid = gridDim.x;
    const int KT = 1 << ktlog;
    const int ntmask = (1 << ntlog) - 1;

    const int warpM = wid >> 2;
    const int warpN = wid & 3;

    if (tid == 0) {
        #pragma unroll
        for (int s = 0; s < STAGES; ++s) {
            MBARRIER_INIT(sbase + 8 * s, 1);
            MBARRIER_INIT(sbase + 64 + 8 * s, 8);
        }
    }
    __syncthreads();

    const int nMy = (bid < Ttiles) ? ((Ttiles - bid - 1) / grid + 1) : 0;
    if (nMy == 0) return;
    const long totIt = (long)nMy << ktlog;

    auto panels = [&](long q, const __half*& pa, const __half*& pb) {
        const int tIdx = (int)(q >> ktlog);
        const int kt   = (int)(q & (KT - 1));
        const int tile = bid + tIdx * grid;
        const int mtq  = tile >> ntlog;
        const int ntq  = tile & ntmask;
        pa = A  + ((size_t)mtq * KT + kt) * (A_ST / 2);
        pb = Bw + ((size_t)ntq * KT + kt) * (B_ST / 2);
    };

    if (tid == 0) {
        #pragma unroll
        for (int s = 0; s < STAGES - 1; ++s) {
            if (s < totIt) {
                const __half *pa, *pb;
                panels(s, pa, pb);
                const uint32_t st = sbase + HDR + s * STG;
                MBARRIER_EXPECT_TX(sbase + 8 * s, STG);
                BULK_G2S(st,        pa, A_ST, sbase + 8 * s);
                BULK_G2S(st + A_ST, pb, B_ST, sbase + 8 * s);
            }
        }
    }

    const int lm   = lid >> 3;
    const int aRow = warpM * 64 + ((lm & 1) << 3) + (lid & 7);
    const int asel = lm >> 1;
    const int aXor = aRow & 7;
    const int bRow = warpN * 64 + ((lm >> 1) << 3) + (lid & 7);
    const int bsel = lm & 1;
    const int bXor = bRow & 7;
    uint32_t aBase[4], bBase[4];
    #pragma unroll
    for (int i = 0; i < 4; ++i) aBase[i] = (uint32_t)(aRow + i * 16) * 128;
    #pragma unroll
    for (int jp = 0; jp < 4; ++jp) bBase[jp] = (uint32_t)(bRow + jp * 16) * 128;

    for (int tl = 0; tl < nMy; ++tl) {
        const int tile = bid + tl * grid;
        const int mt = tile >> ntlog;
        const int nt = tile & ntmask;
        const long m0 = (long)mt * BM;
        const int  n0 = nt * BN;
        const long gbase = (long)tl << ktlog;

        float acc[4][8][4];
        #pragma unroll
        for (int i = 0; i < 4; ++i)
            #pragma unroll
            for (int j = 0; j < 8; ++j)
                #pragma unroll
                for (int e = 0; e < 4; ++e) acc[i][j][e] = 0.0f;

        for (int kt = 0; kt < KT; ++kt) {
            const long gi = gbase + kt;
            const int s = (int)(gi & (STAGES - 1));

            MBARRIER_WAIT_PARITY(sbase + 8 * s, (uint32_t)((gi >> 2) & 1));

            const uint32_t sA = sbase + HDR + s * STG;
            const uint32_t sB = sA + A_ST;

            uint32_t fa[2][4][4], fb[2][4][4];
            {
                const uint32_t aoff = (uint32_t)(((0 + asel) ^ aXor) << 4);
                const uint32_t boff = (uint32_t)(((0 + bsel) ^ bXor) << 4);
                #pragma unroll
                for (int i = 0; i < 4; ++i)    ldsm_x4(fa[0][i],  sA + aBase[i]  + aoff);
                #pragma unroll
                for (int jp = 0; jp < 4; ++jp) ldsm_x4(fb[0][jp], sB + bBase[jp] + boff);
            }

            #pragma unroll
            for (int kk = 0; kk < 4; ++kk) {
                const int cur = kk & 1, nxt = cur ^ 1;
                if (kk < 3) {
                    const uint32_t aoff = (uint32_t)((((kk + 1) * 2 + asel) ^ aXor) << 4);
                    const uint32_t boff = (uint32_t)((((kk + 1) * 2 + bsel) ^ bXor) << 4);
                    #pragma unroll
                    for (int i = 0; i < 4; ++i)    ldsm_x4(fa[nxt][i],  sA + aBase[i]  + aoff);
                    #pragma unroll
                    for (int jp = 0; jp < 4; ++jp) ldsm_x4(fb[nxt][jp], sB + bBase[jp] + boff);
                }
                #pragma unroll
                for (int i = 0; i < 4; ++i)
                    #pragma unroll
                    for (int j = 0; j < 8; ++j)
                        mma_f16(acc[i][j], fa[cur][i], &fb[cur][j >> 1][(j & 1) * 2]);
            }

            const long pf = gi + STAGES - 1;
            if (tid == 0 && pf < totIt) {
                const int s2 = (int)(pf & (STAGES - 1));
                if (pf >= STAGES)
                    MBARRIER_WAIT_PARITY(sbase + 64 + 8 * s2, (uint32_t)(((pf >> 2) - 1) & 1));
                const __half *pa, *pb;
                panels(pf, pa, pb);
                const uint32_t st = sbase + HDR + s2 * STG;
                MBARRIER_EXPECT_TX(sbase + 8 * s2, STG);
                BULK_G2S(st,        pa, A_ST, sbase + 8 * s2);
                BULK_G2S(st + A_ST, pb, B_ST, sbase + 8 * s2);
            }

            __syncwarp();
            if (lid == 0) MBARRIER_ARRIVE(sbase + 64 + 8 * s);
        }

        const bool has2 = (bias2 != nullptr);
        const int jb0 = n0 + warpN * 64;

        #pragma unroll
        for (int j = 0; j < 8; ++j) {
            const int col = jb0 + j * 8 + 2 * tg;
            float bb0 = bias1[col], bb1 = bias1[col + 1];
            if (has2) { bb0 += bias2[col]; bb1 += bias2[col + 1]; }
            #pragma unroll
            for (int i = 0; i < 4; ++i) {
                const long r0 = m0 + warpM * 64 + i * 16 + g;
                #pragma unroll
                for (int h = 0; h < 2; ++h) {
                    const long r = r0 + 8 * h;
                    float v0 = acc[i][j][2 * h + 0] + bb0;
                    float v1 = acc[i][j][2 * h + 1] + bb1;
                    if (RELU) { v0 = fmaxf(v0, 0.0f); v1 = fmaxf(v1, 0.0f); }
                    if (HALF_OUT) {
                        __half2 hv = __floats2half2_rn(v0, v1);
                        const size_t panel = ((size_t)(r >> 7) * (N >> 6) + (col >> 6)) << 13;
                        const size_t off = panel + (size_t)((int)(r & 127)) * 64
                                         + (size_t)(((((col >> 3) & 7) ^ ((int)r & 7)) << 3) + (col & 7));
                        *reinterpret_cast<uint32_t*>((__half*)Cv + off) =
                            *reinterpret_cast<uint32_t*>(&hv);
                    } else {
                        *reinterpret_cast<float2*>((float*)Cv + (size_t)r * N + col) =
                            make_float2(v0, v1);
                    }
                }
            }
        }
    }
}

// ----------------------------------------------------------------------------
// Kernel B (R8 hoist body): persistent GEMM, fp32 out, no relu. GEMM3 only.
// ----------------------------------------------------------------------------
__global__ void __launch_bounds__(NTHR, 1)
gemm_f16_hoist_kernel(const __half* __restrict__ A, const __half* __restrict__ Bw,
                      float* __restrict__ C, const float* __restrict__ bias1,
                      int N, int ktlog, int ntlog, int Ttiles)
{
    extern __shared__ char smem[];
    const uint32_t sbase = smem_u32(smem);
    const int tid = threadIdx.x;
    const int wid = tid >> 5;
    const int lid = tid & 31;
    const int g   = lid >> 2;
    const int tg  = lid & 3;
    const int bid = blockIdx.x;
    const int grid = gridDim.x;
    const int KT = 1 << ktlog;
    const int ntmask = (1 << ntlog) - 1;

    const int warpM = wid >> 2;
    const int warpN = wid & 3;

    if (tid == 0) {
        #pragma unroll
        for (int s = 0; s < STAGES; ++s) {
            MBARRIER_INIT(sbase + 8 * s, 1);
            MBARRIER_INIT(sbase + 64 + 8 * s, 8);
        }
    }
    __syncthreads();

    const int nMy = (bid < Ttiles) ? ((Ttiles - bid - 1) / grid + 1) : 0;
    if (nMy == 0) return;
    const long totIt = (long)nMy << ktlog;

    auto panels = [&](long q, const __half*& pa, const __half*& pb) {
        const int tIdx = (int)(q >> ktlog);
        const int kt   = (int)(q & (KT - 1));
        const int tile = bid + tIdx * grid;
        const int mtq  = tile >> ntlog;
        const int ntq  = tile & ntmask;
        pa = A  + ((size_t)mtq * KT + kt) * (A_ST / 2);
        pb = Bw + ((size_t)ntq * KT + kt) * (B_ST / 2);
    };

    if (tid == 0) {
        #pragma unroll
        for (int s = 0; s < STAGES - 1; ++s) {
            if (s < totIt) {
                const __half *pa, *pb;
                panels(s, pa, pb);
                const uint32_t st = sbase + HDR + s * STG;
                MBARRIER_EXPECT_TX(sbase + 8 * s, STG);
                BULK_G2S(st,        pa, A_ST, sbase + 8 * s);
                BULK_G2S(st + A_ST, pb, B_ST, sbase + 8 * s);
            }
        }
    }

    const int lm   = lid >> 3;
    const int aRow = warpM * 64 + ((lm & 1) << 3) + (lid & 7);
    const int asel = lm >> 1;
    const int aXor = aRow & 7;
    const int bRow = warpN * 64 + ((lm >> 1) << 3) + (lid & 7);
    const int bsel = lm & 1;
    const int bXor = bRow & 7;
    uint32_t aBase[4], bBase[4];
    #pragma unroll
    for (int i = 0; i < 4; ++i) aBase[i] = (uint32_t)(aRow + i * 16) * 128;
    #pragma unroll
    for (int jp = 0; jp < 4; ++jp) bBase[jp] = (uint32_t)(bRow + jp * 16) * 128;

    // fragment double-buffer persists across stage AND tile boundaries
    uint32_t fa[2][4][4], fb[2][4][4];
    {
        MBARRIER_WAIT_PARITY(sbase + 0, 0);
        const uint32_t sA0 = sbase + HDR;
        const uint32_t sB0 = sA0 + A_ST;
        const uint32_t aoff = (uint32_t)(((0 + asel) ^ aXor) << 4);
        const uint32_t boff = (uint32_t)(((0 + bsel) ^ bXor) << 4);
        #pragma unroll
        for (int i = 0; i < 4; ++i)    ldsm_x4(fa[0][i],  sA0 + aBase[i]  + aoff);
        #pragma unroll
        for (int jp = 0; jp < 4; ++jp) ldsm_x4(fb[0][jp], sB0 + bBase[jp] + boff);
    }

    for (int tl = 0; tl < nMy; ++tl) {
        const int tile = bid + tl * grid;
        const int mt = tile >> ntlog;
        const int nt = tile & ntmask;
        const long m0 = (long)mt * BM;
        const int  n0 = nt * BN;
        const long gbase = (long)tl << ktlog;

        float acc[4][8][4];
        #pragma unroll
        for (int i = 0; i < 4; ++i)
            #pragma unroll
            for (int j = 0; j < 8; ++j)
                #pragma unroll
                for (int e = 0; e < 4; ++e) acc[i][j][e] = 0.0f;

        for (int kt = 0; kt < KT; ++kt) {
            const long gi = gbase + kt;
            const int s = (int)(gi & (STAGES - 1));
            const uint32_t sA = sbase + HDR + s * STG;
            const uint32_t sB = sA + A_ST;

            #pragma unroll
            for (int kk = 0; kk < 3; ++kk) {
                const int cur = kk & 1, nxt = cur ^ 1;
                const uint32_t aoff = (uint32_t)((((kk + 1) * 2 + asel) ^ aXor) << 4);
                const uint32_t boff = (uint32_t)((((kk + 1) * 2 + bsel) ^ bXor) << 4);
                #pragma unroll
                for (int i = 0; i < 4; ++i)    ldsm_x4(fa[nxt][i],  sA + aBase[i]  + aoff);
                #pragma unroll
                for (int jp = 0; jp < 4; ++jp) ldsm_x4(fb[nxt][jp], sB + bBase[jp] + boff);
                #pragma unroll
                for (int i = 0; i < 4; ++i)
                    #pragma unroll
                    for (int j = 0; j < 8; ++j)
                        mma_f16(acc[i][j], fa[cur][i], &fb[cur][j >> 1][(j & 1) * 2]);
            }

            // kk = 3: wait NEXT stage + preload its kk=0 fragments before
            // issuing kk=3's 32 MMAs — the wait is covered by queued MMA work.
            if (gi + 1 < totIt) {
                const int sn = (int)((gi + 1) & (STAGES - 1));
                MBARRIER_WAIT_PARITY(sbase + 8 * sn, (uint32_t)(((gi + 1) >> 2) & 1));
                const uint32_t sAn = sbase + HDR + sn * STG;
                const uint32_t sBn = sAn + A_ST;
                const uint32_t aoff = (uint32_t)(((0 + asel) ^ aXor) << 4);
                const uint32_t boff = (uint32_t)(((0 + bsel) ^ bXor) << 4);
                #pragma unroll
                for (int i = 0; i < 4; ++i)    ldsm_x4(fa[0][i],  sAn + aBase[i]  + aoff);
                #pragma unroll
                for (int jp = 0; jp < 4; ++jp) ldsm_x4(fb[0][jp], sBn + bBase[jp] + boff);
            }
            #pragma unroll
            for (int i = 0; i < 4; ++i)
                #pragma unroll
                for (int j = 0; j < 8; ++j)
                    mma_f16(acc[i][j], fa[1][i], &fb[1][j >> 1][(j & 1) * 2]);

            __syncwarp();
            if (lid == 0) MBARRIER_ARRIVE(sbase + 64 + 8 * s);

            const long pf = gi + STAGES - 1;
            if (tid == 0 && pf < totIt) {
                const int s2 = (int)(pf & (STAGES - 1));
                if (pf >= STAGES)
                    MBARRIER_WAIT_PARITY(sbase + 64 + 8 * s2, (uint32_t)(((pf >> 2) - 1) & 1));
                const __half *pa, *pb;
                panels(pf, pa, pb);
                const uint32_t st = sbase + HDR + s2 * STG;
                MBARRIER_EXPECT_TX(sbase + 8 * s2, STG);
                BULK_G2S(st,        pa, A_ST, sbase + 8 * s2);
                BULK_G2S(st + A_ST, pb, B_ST, sbase + 8 * s2);
            }
        }

        // ---- epilogue: bias + fp32 store -----------------------------------
        const int jb0 = n0 + warpN * 64;
        #pragma unroll
        for (int j = 0; j < 8; ++j) {
            const int col = jb0 + j * 8 + 2 * tg;
            const float bb0 = bias1[col], bb1 = bias1[col + 1];
            #pragma unroll
            for (int i = 0; i < 4; ++i) {
                const long r0 = m0 + warpM * 64 + i * 16 + g;
                #pragma unroll
                for (int h = 0; h < 2; ++h) {
                    const long r = r0 + 8 * h;
                    *reinterpret_cast<float2*>(C + (size_t)r * N + col) =
                        make_float2(acc[i][j][2 * h + 0] + bb0,
                                    acc[i][j][2 * h + 1] + bb1);
                }
            }
        }
    }
}

// ----------------------------------------------------------------------------
// Host launcher
// ----------------------------------------------------------------------------
extern "C" void kernel_launch(void* const* d_in, const int* in_sizes, int n_in,
                              void* d_out, int out_size)
{
    const float* x    = (const float*)d_in[0];
    const float* W1   = (const float*)d_in[1];
    const float* b1   = (const float*)d_in[2];
    const float* W2   = (const float*)d_in[3];
    const float* bih  = (const float*)d_in[4];
    const float* bhh  = (const float*)d_in[5];
    const float* W3   = (const float*)d_in[6];
    const float* b3   = (const float*)d_in[7];
    float* out = (float*)d_out;

    __half *gx, *gh, *go, *gw1, *gw2, *gw3;
    cudaGetSymbolAddress((void**)&gx,  g_x);
    cudaGetSymbolAddress((void**)&gh,  g_h);
    cudaGetSymbolAddress((void**)&go,  g_o);
    cudaGetSymbolAddress((void**)&gw1, g_w1);
    cudaGetSymbolAddress((void**)&gw2, g_w2);
    cudaGetSymbolAddress((void**)&gw3, g_w3);

    cudaFuncSetAttribute(gemm_f16_kernel<true, true>,
                         cudaFuncAttributeMaxDynamicSharedMemorySize, SMEM_TOTAL);
    cudaFuncSetAttribute(gemm_f16_hoist_kernel,
                         cudaFuncAttributeMaxDynamicSharedMemorySize, SMEM_TOTAL);

    int nsm = 148;
    cudaDeviceGetAttribute(&nsm, cudaDevAttrMultiProcessorCount, 0);

    // fused pre-pass: fp32 -> fp16 into swizzled panels (single launch)
    {
        CvtSeg s0 = { x,  gx,  (int)(MTOK * (long)DIN / 8), 7, 7 };   // RP=128
        CvtSeg s1 = { W1, gw1, (int)((long)DH * DIN / 8),   7, 8 };   // RP=256
        CvtSeg s2 = { W2, gw2, (int)((long)DH * DH / 8),    8, 8 };
        CvtSeg s3 = { W3, gw3, (int)((long)DACT * DH / 8),  8, 8 };
        const int total = s0.ng + s1.ng + s2.ng + s3.ng;
        cvt_all_kernel<<<2048, 512>>>(s0, s1, s2, s3, total);
    }

    const int Mtiles = (int)(MTOK / BM);   // 256

    // GEMM1: h = relu(x @ W1^T + b1) -> fp16 panels   (KT=16, ktlog=4, ntlog=3)
    gemm_f16_kernel<true, true><<<nsm, NTHR, SMEM_TOTAL>>>(
        gx, gw1, gh, b1, nullptr, DH, 4, 3, Mtiles * (DH / BN));

    // GEMM2: o = relu(h @ W2^T + bih + bhh) -> fp16 panels (KT=32, ktlog=5, ntlog=3)
    gemm_f16_kernel<true, true><<<nsm, NTHR, SMEM_TOTAL>>>(
        gh, gw2, go, bih, bhh, DH, 5, 3, Mtiles * (DH / BN));

    // GEMM3: y = o @ W3^T + b3 -> fp32 row-major (KT=32, ktlog=5, ntlog=2, hoist)
    gemm_f16_hoist_kernel<<<nsm, NTHR, SMEM_TOTAL>>>(
        go, gw3, out, b3, DACT, 5, 2, Mtiles * (DACT / BN));

    (void)in_sizes; (void)n_in; (void)out_size;
}

// round 15
// speedup vs baseline: 1.9950x; 1.0108x over previous
#include <cuda_runtime.h>
#include <cuda_fp16.h>
#include <cstdint>

// ----------------------------------------------------------------------------
// R14 = R13 + remainder-wave splitting for GEMM1/2:
//   main kernel runs exactly floor(T/nsm)*nsm tiles (zero tail),
//   a separate BM=64 "rem" kernel runs the remaining tiles as 2x M-halves
//   (half-duration final wave instead of a full one).
//   gemm_f16_kernel       (R7 body)   : GEMM1/2 main, fp16 panel out
//   gemm_f16_rem64_kernel (new, BM=64): GEMM1/2 remainder halves
//   gemm_f16_hoist_kernel (R8 body)   : GEMM3, fp32 out
//
//   h = relu(x @ W_init^T + b_init)        M=32768 N=2048 K=1024
//   o = relu(h @ W_ih^T  + b_ih + b_hh)    M=32768 N=2048 K=2048
//   y =       o @ W_final^T + b_final      M=32768 N=1024 K=2048
// ----------------------------------------------------------------------------

#define DINLINE __device__ __forceinline__

static constexpr int DIN  = 1024;
static constexpr int DH   = 2048;
static constexpr int DACT = 1024;
static constexpr long MTOK = 32768;

static constexpr int BM = 128;
static constexpr int BN = 256;
static constexpr int BK = 64;            // 128B rows
static constexpr int STAGES = 4;
static constexpr int NTHR = 256;

static constexpr int A_ST = BM * BK * 2;         // 16384 B
static constexpr int B_ST = BN * BK * 2;         // 32768 B
static constexpr int STG  = A_ST + B_ST;         // 49152 B
static constexpr int HDR  = 1024;
static constexpr int SMEM_TOTAL = HDR + STAGES * STG;   // 197632

// rem kernel (BM=64)
static constexpr int A_HST = 64 * BK * 2;        // 8192 B
static constexpr int STG_H = A_HST + B_ST;       // 40960 B
static constexpr int SMEM_REM = HDR + STAGES * STG_H;   // 164864

DINLINE uint32_t smem_u32(const void* p) {
    uint32_t a;
    asm("{ .reg .u64 t; cvta.to.shared.u64 t, %1; cvt.u32.u64 %0, t; }"
        : "=r"(a) : "l"(p));
    return a;
}

#define MBARRIER_INIT(addr, cnt) \
    asm volatile("mbarrier.init.shared.b64 [%0], %1;" :: "r"(addr), "r"(cnt) : "memory")
#define MBARRIER_ARRIVE(addr) \
    asm volatile("mbarrier.arrive.shared.b64 _, [%0];" :: "r"(addr) : "memory")
#define MBARRIER_EXPECT_TX(addr, n) \
    asm volatile("mbarrier.arrive.expect_tx.shared.b64 _, [%0], %1;" :: "r"(addr), "r"(n) : "memory")

#define MBARRIER_WAIT_PARITY(mbar_smem_addr, phase_parity) do { \
    uint32_t _mbar = (uint32_t)(mbar_smem_addr); \
    uint32_t _parity = (uint32_t)(phase_parity); \
    uint32_t _done; \
    asm volatile( \
        "{\n\t" \
        ".reg .pred p;\n\t" \
        "mbarrier.try_wait.parity.shared.b64 p, [%1], %2;\n\t" \
        "selp.b32 %0, 1, 0, p;\n\t" \
        "}" \
        : "=r"(_done) : "r"(_mbar), "r"(_parity) : "memory"); \
    if (!_done) { \
        asm volatile( \
            "{\n\t" \
            ".reg .pred P1;\n\t" \
            "WAIT_LOOP_%=:\n\t" \
            "mbarrier.try_wait.parity.shared.b64 P1, [%0], %1, 0x989680;\n\t" \
            "@P1 bra.uni WAIT_DONE_%=;\n\t" \
            "bra.uni WAIT_LOOP_%=;\n\t" \
            "WAIT_DONE_%=:\n\t" \
            "}" \
            :: "r"(_mbar), "r"(_parity) : "memory"); \
    } \
} while(0)

#define BULK_G2S(dst, src, sz, mbar) \
    asm volatile("cp.async.bulk.shared::cta.global.mbarrier::complete_tx::bytes [%0], [%1], %2, [%3];" \
        :: "r"((uint32_t)(dst)), "l"(src), "r"((uint32_t)(sz)), "r"((uint32_t)(mbar)) : "memory")

DINLINE void ldsm_x4(uint32_t* r, uint32_t addr) {
    asm volatile("ldmatrix.sync.aligned.m8n8.x4.shared.b16 {%0,%1,%2,%3}, [%4];"
        : "=r"(r[0]), "=r"(r[1]), "=r"(r[2]), "=r"(r[3]) : "r"(addr));
}

DINLINE void mma_f16(float* c, const uint32_t* a, const uint32_t* b) {
    asm volatile(
        "mma.sync.aligned.m16n8k16.row.col.f32.f16.f16.f32 "
        "{%0,%1,%2,%3}, {%4,%5,%6,%7}, {%8,%9}, {%0,%1,%2,%3};"
        : "+f"(c[0]), "+f"(c[1]), "+f"(c[2]), "+f"(c[3])
        : "r"(a[0]), "r"(a[1]), "r"(a[2]), "r"(a[3]), "r"(b[0]), "r"(b[1]));
}

// ----------------------------------------------------------------------------
// Scratch (static device allocations -- allowed). All in swizzled panel layout.
// ----------------------------------------------------------------------------
__device__ __half g_x [MTOK * DIN];
__device__ __half g_h [MTOK * DH];
__device__ __half g_o [MTOK * DH];
__device__ __half g_w1[(long)DH * DIN];
__device__ __half g_w2[(long)DH * DH];
__device__ __half g_w3[(long)DACT * DH];

// ----------------------------------------------------------------------------
// Fused fp32 -> fp16 + tile/swizzle pre-pass (all four tensors, one launch).
// ----------------------------------------------------------------------------
struct CvtSeg {
    const float* in;
    __half* out;
    int ng;        // granule count
    int kshift;    // log2(K/8)
    int rplog;     // log2(RP)
};

__global__ void __launch_bounds__(512, 2)
cvt_all_kernel(CvtSeg s0, CvtSeg s1, CvtSeg s2, CvtSeg s3, int total)
{
    for (int gi0 = blockIdx.x * blockDim.x + threadIdx.x; gi0 < total;
         gi0 += gridDim.x * blockDim.x) {
        CvtSeg s; int gi = gi0;
        if (gi < s0.ng) s = s0;
        else {
            gi -= s0.ng;
            if (gi < s1.ng) s = s1;
            else {
                gi -= s1.ng;
                if (gi < s2.ng) s = s2;
                else { gi -= s2.ng; s = s3; }
            }
        }
        const int gperrow = 1 << s.kshift;
        const int c8 = gi & (gperrow - 1);
        const int r  = gi >> s.kshift;
        const float4* f4 = reinterpret_cast<const float4*>(s.in);
        float4 v0 = f4[2 * (size_t)gi], v1 = f4[2 * (size_t)gi + 1];
        __half2 h0 = __floats2half2_rn(v0.x, v0.y), h1 = __floats2half2_rn(v0.z, v0.w);
        __half2 h2 = __floats2half2_rn(v1.x, v1.y), h3 = __floats2half2_rn(v1.z, v1.w);
        uint4 o = make_uint4(*reinterpret_cast<uint32_t*>(&h0), *reinterpret_cast<uint32_t*>(&h1),
                             *reinterpret_cast<uint32_t*>(&h2), *reinterpret_cast<uint32_t*>(&h3));
        const int rp = 1 << s.rplog;
        const size_t panel = (size_t)(r >> s.rplog) * (gperrow >> 3) + (c8 >> 3);
        const size_t gip   = (size_t)(r & (rp - 1)) * 8 + ((c8 & 7) ^ (r & 7));
        reinterpret_cast<uint4*>(s.out)[panel * ((size_t)rp * 8) + gip] = o;
    }
}

// ----------------------------------------------------------------------------
// Kernel A (R7 verbatim): persistent GEMM, fp16 panel out + relu.
// ----------------------------------------------------------------------------
template <bool HALF_OUT, bool RELU>
__global__ void __launch_bounds__(NTHR, 1)
gemm_f16_kernel(const __half* __restrict__ A, const __half* __restrict__ Bw,
                void* __restrict__ Cv,
                const float* __restrict__ bias1, const float* __restrict__ bias2,
                int N, int ktlog, int ntlog, int Ttiles)
{
    extern __shared__ char smem[];
    const uint32_t sbase = smem_u32(smem);
    const int tid = threadIdx.x;
    const int wid = tid >> 5;
    const int lid = tid & 31;
    const int g   = lid >> 2;
    const int tg  = lid & 3;
    const int bid = blockIdx.x;
    const int grid = gridDim.x;
    const int KT = 1 << ktlog;
    const int ntmask = (1 << ntlog) - 1;

    const int warpM = wid >> 2;
    const int warpN = wid & 3;

    if (tid == 0) {
        #pragma unroll
        for (int s = 0; s < STAGES; ++s) {
            MBARRIER_INIT(sbase + 8 * s, 1);
            MBARRIER_INIT(sbase + 64 + 8 * s, 8);
        }
    }
    __syncthreads();

    const int nMy = (bid < Ttiles) ? ((Ttiles - bid - 1) / grid + 1) : 0;
    if (nMy == 0) return;
    const long totIt = (long)nMy << ktlog;

    auto panels = [&](long q, const __half*& pa, const __half*& pb) {
        const int tIdx = (int)(q >> ktlog);
        const int kt   = (int)(q & (KT - 1));
        const int tile = bid + tIdx * grid;
        const int mtq  = tile >> ntlog;
        const int ntq  = tile & ntmask;
        pa = A  + ((size_t)mtq * KT + kt) * (A_ST / 2);
        pb = Bw + ((size_t)ntq * KT + kt) * (B_ST / 2);
    };

    if (tid == 0) {
        #pragma unroll
        for (int s = 0; s < STAGES - 1; ++s) {
            if (s < totIt) {
                const __half *pa, *pb;
                panels(s, pa, pb);
                const uint32_t st = sbase + HDR + s * STG;
                MBARRIER_EXPECT_TX(sbase + 8 * s, STG);
                BULK_G2S(st,        pa, A_ST, sbase + 8 * s);
                BULK_G2S(st + A_ST, pb, B_ST, sbase + 8 * s);
            }
        }
    }

    const int lm   = lid >> 3;
    const int aRow = warpM * 64 + ((lm & 1) << 3) + (lid & 7);
    const int asel = lm >> 1;
    const int aXor = aRow & 7;
    const int bRow = warpN * 64 + ((lm >> 1) << 3) + (lid & 7);
    const int bsel = lm & 1;
    const int bXor = bRow & 7;
    uint32_t aBase[4], bBase[4];
    #pragma unroll
    for (int i = 0; i < 4; ++i) aBase[i] = (uint32_t)(aRow + i * 16) * 128;
    #pragma unroll
    for (int jp = 0; jp < 4; ++jp) bBase[jp] = (uint32_t)(bRow + jp * 16) * 128;

    for (int tl = 0; tl < nMy; ++tl) {
        const int tile = bid + tl * grid;
        const int mt = tile >> ntlog;
        const int nt = tile & ntmask;
        const long m0 = (long)mt * BM;
        const int  n0 = nt * BN;
        const long gbase = (long)tl << ktlog;

        float acc[4][8][4];
        #pragma unroll
        for (int i = 0; i < 4; ++i)
            #pragma unroll
            for (int j = 0; j < 8; ++j)
                #pragma unroll
                for (int e = 0; e < 4; ++e) acc[i][j][e] = 0.0f;

        for (int kt = 0; kt < KT; ++kt) {
            const long gi = gbase + kt;
            const int s = (int)(gi & (STAGES - 1));

            MBARRIER_WAIT_PARITY(sbase + 8 * s, (uint32_t)((gi >> 2) & 1));

            const uint32_t sA = sbase + HDR + s * STG;
            const uint32_t sB = sA + A_ST;

            uint32_t fa[2][4][4], fb[2][4][4];
            {
                const uint32_t aoff = (uint32_t)(((0 + asel) ^ aXor) << 4);
                const uint32_t boff = (uint32_t)(((0 + bsel) ^ bXor) << 4);
                #pragma unroll
                for (int i = 0; i < 4; ++i)    ldsm_x4(fa[0][i],  sA + aBase[i]  + aoff);
                #pragma unroll
                for (int jp = 0; jp < 4; ++jp) ldsm_x4(fb[0][jp], sB + bBase[jp] + boff);
            }

            #pragma unroll
            for (int kk = 0; kk < 4; ++kk) {
                const int cur = kk & 1, nxt = cur ^ 1;
                if (kk < 3) {
                    const uint32_t aoff = (uint32_t)((((kk + 1) * 2 + asel) ^ aXor) << 4);
                    const uint32_t boff = (uint32_t)((((kk + 1) * 2 + bsel) ^ bXor) << 4);
                    #pragma unroll
                    for (int i = 0; i < 4; ++i)    ldsm_x4(fa[nxt][i],  sA + aBase[i]  + aoff);
                    #pragma unroll
                    for (int jp = 0; jp < 4; ++jp) ldsm_x4(fb[nxt][jp], sB + bBase[jp] + boff);
                }
                #pragma unroll
                for (int i = 0; i < 4; ++i)
                    #pragma unroll
                    for (int j = 0; j < 8; ++j)
                        mma_f16(acc[i][j], fa[cur][i], &fb[cur][j >> 1][(j & 1) * 2]);
            }

            const long pf = gi + STAGES - 1;
            if (tid == 0 && pf < totIt) {
                const int s2 = (int)(pf & (STAGES - 1));
                if (pf >= STAGES)
                    MBARRIER_WAIT_PARITY(sbase + 64 + 8 * s2, (uint32_t)(((pf >> 2) - 1) & 1));
                const __half *pa, *pb;
                panels(pf, pa, pb);
                const uint32_t st = sbase + HDR + s2 * STG;
                MBARRIER_EXPECT_TX(sbase + 8 * s2, STG);
                BULK_G2S(st,        pa, A_ST, sbase + 8 * s2);
                BULK_G2S(st + A_ST, pb, B_ST, sbase + 8 * s2);
            }

            __syncwarp();
            if (lid == 0) MBARRIER_ARRIVE(sbase + 64 + 8 * s);
        }

        const bool has2 = (bias2 != nullptr);
        const int jb0 = n0 + warpN * 64;

        #pragma unroll
        for (int j = 0; j < 8; ++j) {
            const int col = jb0 + j * 8 + 2 * tg;
            float bb0 = bias1[col], bb1 = bias1[col + 1];
            if (has2) { bb0 += bias2[col]; bb1 += bias2[col + 1]; }
            #pragma unroll
            for (int i = 0; i < 4; ++i) {
                const long r0 = m0 + warpM * 64 + i * 16 + g;
                #pragma unroll
                for (int h = 0; h < 2; ++h) {
                    const long r = r0 + 8 * h;
                    float v0 = acc[i][j][2 * h + 0] + bb0;
                    float v1 = acc[i][j][2 * h + 1] + bb1;
                    if (RELU) { v0 = fmaxf(v0, 0.0f); v1 = fmaxf(v1, 0.0f); }
                    if (HALF_OUT) {
                        __half2 hv = __floats2half2_rn(v0, v1);
                        const size_t panel = ((size_t)(r >> 7) * (N >> 6) + (col >> 6)) << 13;
                        const size_t off = panel + (size_t)((int)(r & 127)) * 64
                                         + (size_t)(((((col >> 3) & 7) ^ ((int)r & 7)) << 3) + (col & 7));
                        *reinterpret_cast<uint32_t*>((__half*)Cv + off) =
                            *reinterpret_cast<uint32_t*>(&hv);
                    } else {
                        *reinterpret_cast<float2*>((float*)Cv + (size_t)r * N + col) =
                            make_float2(v0, v1);
                    }
                }
            }
        }
    }
}

// ----------------------------------------------------------------------------
// Kernel R (new): BM=64 remainder kernel, fp16 panel out + relu.
// Jobs = remainder tiles x 2 M-halves; job j -> tile tileBase + (j>>1),
// rows [mhalf*64, mhalf*64+64). Warp tile 32x64 (acc 64 regs).
// ----------------------------------------------------------------------------
__global__ void __launch_bounds__(NTHR, 1)
gemm_f16_rem64_kernel(const __half* __restrict__ A, const __half* __restrict__ Bw,
                      __half* __restrict__ Cv,
                      const float* __restrict__ bias1, const float* __restrict__ bias2,
                      int N, int ktlog, int ntlog, int tileBase, int njobs)
{
    extern __shared__ char smem[];
    const uint32_t sbase = smem_u32(smem);
    const int tid = threadIdx.x;
    const int wid = tid >> 5;
    const int lid = tid & 31;
    const int g   = lid >> 2;
    const int tg  = lid & 3;
    const int bid = blockIdx.x;
    const int grid = gridDim.x;
    const int KT = 1 << ktlog;
    const int ntmask = (1 << ntlog) - 1;

    const int warpM = wid >> 2;      // 0..1 (32-row slabs)
    const int warpN = wid & 3;

    if (tid == 0) {
        #pragma unroll
        for (int s = 0; s < STAGES; ++s) {
            MBARRIER_INIT(sbase + 8 * s, 1);
            MBARRIER_INIT(sbase + 64 + 8 * s, 8);
        }
    }
    __syncthreads();

    const int nMy = (bid < njobs) ? ((njobs - bid - 1) / grid + 1) : 0;
    if (nMy == 0) return;
    const long totIt = (long)nMy << ktlog;

    auto panels = [&](long q, const __half*& pa, const __half*& pb) {
        const int jIdx = (int)(q >> ktlog);
        const int kt   = (int)(q & (KT - 1));
        const int job  = bid + jIdx * grid;
        const int tile = tileBase + (job >> 1);
        const int mh   = job & 1;
        const int mtq  = tile >> ntlog;
        const int ntq  = tile & ntmask;
        pa = A  + ((size_t)mtq * KT + kt) * (A_ST / 2) + (size_t)mh * (A_HST / 2);
        pb = Bw + ((size_t)ntq * KT + kt) * (B_ST / 2);
    };

    if (tid == 0) {
        #pragma unroll
        for (int s = 0; s < STAGES - 1; ++s) {
            if (s < totIt) {
                const __half *pa, *pb;
                panels(s, pa, pb);
                const uint32_t st = sbase + HDR + s * STG_H;
                MBARRIER_EXPECT_TX(sbase + 8 * s, STG_H);
                BULK_G2S(st,         pa, A_HST, sbase + 8 * s);
                BULK_G2S(st + A_HST, pb, B_ST,  sbase + 8 * s);
            }
        }
    }

    const int lm   = lid >> 3;
    const int aRow = warpM * 32 + ((lm & 1) << 3) + (lid & 7);
    const int asel = lm >> 1;
    const int aXor = aRow & 7;
    const int bRow = warpN * 64 + ((lm >> 1) << 3) + (lid & 7);
    const int bsel = lm & 1;
    const int bXor = bRow & 7;
    uint32_t aBase[2], bBase[4];
    #pragma unroll
    for (int i = 0; i < 2; ++i) aBase[i] = (uint32_t)(aRow + i * 16) * 128;
    #pragma unroll
    for (int jp = 0; jp < 4; ++jp) bBase[jp] = (uint32_t)(bRow + jp * 16) * 128;

    for (int jl = 0; jl < nMy; ++jl) {
        const int job  = bid + jl * grid;
        const int tile = tileBase + (job >> 1);
        const int mh   = job & 1;
        const int mt = tile >> ntlog;
        const int nt = tile & ntmask;
        const long m0 = (long)mt * BM + (long)mh * 64;
        const int  n0 = nt * BN;
        const long gbase = (long)jl << ktlog;

        float acc[2][8][4];
        #pragma unroll
        for (int i = 0; i < 2; ++i)
            #pragma unroll
            for (int j = 0; j < 8; ++j)
                #pragma unroll
                for (int e = 0; e < 4; ++e) acc[i][j][e] = 0.0f;

        for (int kt = 0; kt < KT; ++kt) {
            const long gi = gbase + kt;
            const int s = (int)(gi & (STAGES - 1));

            MBARRIER_WAIT_PARITY(sbase + 8 * s, (uint32_t)((gi >> 2) & 1));

            const uint32_t sA = sbase + HDR + s * STG_H;
            const uint32_t sB = sA + A_HST;

            uint32_t fa[2][2][4], fb[2][4][4];
            {
                const uint32_t aoff = (uint32_t)(((0 + asel) ^ aXor) << 4);
                const uint32_t boff = (uint32_t)(((0 + bsel) ^ bXor) << 4);
                #pragma unroll
                for (int i = 0; i < 2; ++i)    ldsm_x4(fa[0][i],  sA + aBase[i]  + aoff);
                #pragma unroll
                for (int jp = 0; jp < 4; ++jp) ldsm_x4(fb[0][jp], sB + bBase[jp] + boff);
            }

            #pragma unroll
            for (int kk = 0; kk < 4; ++kk) {
                const int cur = kk & 1, nxt = cur ^ 1;
                if (kk < 3) {
                    const uint32_t aoff = (uint32_t)((((kk + 1) * 2 + asel) ^ aXor) << 4);
                    const uint32_t boff = (uint32_t)((((kk + 1) * 2 + bsel) ^ bXor) << 4);
                    #pragma unroll
                    for (int i = 0; i < 2; ++i)    ldsm_x4(fa[nxt][i],  sA + aBase[i]  + aoff);
                    #pragma unroll
                    for (int jp = 0; jp < 4; ++jp) ldsm_x4(fb[nxt][jp], sB + bBase[jp] + boff);
                }
                #pragma unroll
                for (int i = 0; i < 2; ++i)
                    #pragma unroll
                    for (int j = 0; j < 8; ++j)
                        mma_f16(acc[i][j], fa[cur][i], &fb[cur][j >> 1][(j & 1) * 2]);
            }

            const long pf = gi + STAGES - 1;
            if (tid == 0 && pf < totIt) {
                const int s2 = (int)(pf & (STAGES - 1));
                if (pf >= STAGES)
                    MBARRIER_WAIT_PARITY(sbase + 64 + 8 * s2, (uint32_t)(((pf >> 2) - 1) & 1));
                const __half *pa, *pb;
                panels(pf, pa, pb);
                const uint32_t st = sbase + HDR + s2 * STG_H;
                MBARRIER_EXPECT_TX(sbase + 8 * s2, STG_H);
                BULK_G2S(st,         pa, A_HST, sbase + 8 * s2);
                BULK_G2S(st + A_HST, pb, B_ST,  sbase + 8 * s2);
            }

            __syncwarp();
            if (lid == 0) MBARRIER_ARRIVE(sbase + 64 + 8 * s);
        }

        const bool has2 = (bias2 != nullptr);
        const int jb0 = n0 + warpN * 64;

        #pragma unroll
        for (int j = 0; j < 8; ++j) {
            const int col = jb0 + j * 8 + 2 * tg;
            float bb0 = bias1[col], bb1 = bias1[col + 1];
            if (has2) { bb0 += bias2[col]; bb1 += bias2[col + 1]; }
            #pragma unroll
            for (int i = 0; i < 2; ++i) {
                const long r0 = m0 + warpM * 32 + i * 16 + g;
                #pragma unroll
                for (int h = 0; h < 2; ++h) {
                    const long r = r0 + 8 * h;
                    float v0 = fmaxf(acc[i][j][2 * h + 0] + bb0, 0.0f);
                    float v1 = fmaxf(acc[i][j][2 * h + 1] + bb1, 0.0f);
                    __half2 hv = __floats2half2_rn(v0, v1);
                    const size_t panel = ((size_t)(r >> 7) * (N >> 6) + (col >> 6)) << 13;
                    const size_t off = panel + (size_t)((int)(r & 127)) * 64
                                     + (size_t)(((((col >> 3) & 7) ^ ((int)r & 7)) << 3) + (col & 7));
                    *reinterpret_cast<uint32_t*>(Cv + off) =
                        *reinterpret_cast<uint32_t*>(&hv);
                }
            }
        }
    }
}

// ----------------------------------------------------------------------------
// Kernel B (R8 hoist body): persistent GEMM, fp32 out, no relu. GEMM3 only.
// ----------------------------------------------------------------------------
__global__ void __launch_bounds__(NTHR, 1)
gemm_f16_hoist_kernel(const __half* __restrict__ A, const __half* __restrict__ Bw,
                      float* __restrict__ C, const float* __restrict__ bias1,
                      int N, int ktlog, int ntlog, int Ttiles)
{
    extern __shared__ char smem[];
    const uint32_t sbase = smem_u32(smem);
    const int tid = threadIdx.x;
    const int wid = tid >> 5;
    const int lid = tid & 31;
    const int g   = lid >> 2;
    const int tg  = lid & 3;
    const int bid = blockIdx.x;
    const int grid = gridDim.x;
    const int KT = 1 << ktlog;
    const int ntmask = (1 << ntlog) - 1;

    const int warpM = wid >> 2;
    const int warpN = wid & 3;

    if (tid == 0) {
        #pragma unroll
        for (int s = 0; s < STAGES; ++s) {
            MBARRIER_INIT(sbase + 8 * s, 1);
            MBARRIER_INIT(sbase + 64 + 8 * s, 8);
        }
    }
    __syncthreads();

    const int nMy = (bid < Ttiles) ? ((Ttiles - bid - 1) / grid + 1) : 0;
    if (nMy == 0) return;
    const long totIt = (long)nMy << ktlog;

    auto panels = [&](long q, const __half*& pa, const __half*& pb) {
        const int tIdx = (int)(q >> ktlog);
        const int kt   = (int)(q & (KT - 1));
        const int tile = bid + tIdx * grid;
        const int mtq  = tile >> ntlog;
        const int ntq  = tile & ntmask;
        pa = A  + ((size_t)mtq * KT + kt) * (A_ST / 2);
        pb = Bw + ((size_t)ntq * KT + kt) * (B_ST / 2);
    };

    if (tid == 0) {
        #pragma unroll
        for (int s = 0; s < STAGES - 1; ++s) {
            if (s < totIt) {
                const __half *pa, *pb;
                panels(s, pa, pb);
                const uint32_t st = sbase + HDR + s * STG;
                MBARRIER_EXPECT_TX(sbase + 8 * s, STG);
                BULK_G2S(st,        pa, A_ST, sbase + 8 * s);
                BULK_G2S(st + A_ST, pb, B_ST, sbase + 8 * s);
            }
        }
    }

    const int lm   = lid >> 3;
    const int aRow = warpM * 64 + ((lm & 1) << 3) + (lid & 7);
    const int asel = lm >> 1;
    const int aXor = aRow & 7;
    const int bRow = warpN * 64 + ((lm >> 1) << 3) + (lid & 7);
    const int bsel = lm & 1;
    const int bXor = bRow & 7;
    uint32_t aBase[4], bBase[4];
    #pragma unroll
    for (int i = 0; i < 4; ++i) aBase[i] = (uint32_t)(aRow + i * 16) * 128;
    #pragma unroll
    for (int jp = 0; jp < 4; ++jp) bBase[jp] = (uint32_t)(bRow + jp * 16) * 128;

    // fragment double-buffer persists across stage AND tile boundaries
    uint32_t fa[2][4][4], fb[2][4][4];
    {
        MBARRIER_WAIT_PARITY(sbase + 0, 0);
        const uint32_t sA0 = sbase + HDR;
        const uint32_t sB0 = sA0 + A_ST;
        const uint32_t aoff = (uint32_t)(((0 + asel) ^ aXor) << 4);
        const uint32_t boff = (uint32_t)(((0 + bsel) ^ bXor) << 4);
        #pragma unroll
        for (int i = 0; i < 4; ++i)    ldsm_x4(fa[0][i],  sA0 + aBase[i]  + aoff);
        #pragma unroll
        for (int jp = 0; jp < 4; ++jp) ldsm_x4(fb[0][jp], sB0 + bBase[jp] + boff);
    }

    for (int tl = 0; tl < nMy; ++tl) {
        const int tile = bid + tl * grid;
        const int mt = tile >> ntlog;
        const int nt = tile & ntmask;
        const long m0 = (long)mt * BM;
        const int  n0 = nt * BN;
        const long gbase = (long)tl << ktlog;

        float acc[4][8][4];
        #pragma unroll
        for (int i = 0; i < 4; ++i)
            #pragma unroll
            for (int j = 0; j < 8; ++j)
                #pragma unroll
                for (int e = 0; e < 4; ++e) acc[i][j][e] = 0.0f;

        for (int kt = 0; kt < KT; ++kt) {
            const long gi = gbase + kt;
            const int s = (int)(gi & (STAGES - 1));
            const uint32_t sA = sbase + HDR + s * STG;
            const uint32_t sB = sA + A_ST;

            #pragma unroll
            for (int kk = 0; kk < 3; ++kk) {
                const int cur = kk & 1, nxt = cur ^ 1;
                const uint32_t aoff = (uint32_t)((((kk + 1) * 2 + asel) ^ aXor) << 4);
                const uint32_t boff = (uint32_t)((((kk + 1) * 2 + bsel) ^ bXor) << 4);
                #pragma unroll
                for (int i = 0; i < 4; ++i)    ldsm_x4(fa[nxt][i],  sA + aBase[i]  + aoff);
                #pragma unroll
                for (int jp = 0; jp < 4; ++jp) ldsm_x4(fb[nxt][jp], sB + bBase[jp] + boff);
                #pragma unroll
                for (int i = 0; i < 4; ++i)
                    #pragma unroll
                    for (int j = 0; j < 8; ++j)
                        mma_f16(acc[i][j], fa[cur][i], &fb[cur][j >> 1][(j & 1) * 2]);
            }

            if (gi + 1 < totIt) {
                const int sn = (int)((gi + 1) & (STAGES - 1));
                MBARRIER_WAIT_PARITY(sbase + 8 * sn, (uint32_t)(((gi + 1) >> 2) & 1));
                const uint32_t sAn = sbase + HDR + sn * STG;
                const uint32_t sBn = sAn + A_ST;
                const uint32_t aoff = (uint32_t)(((0 + asel) ^ aXor) << 4);
                const uint32_t boff = (uint32_t)(((0 + bsel) ^ bXor) << 4);
                #pragma unroll
                for (int i = 0; i < 4; ++i)    ldsm_x4(fa[0][i],  sAn + aBase[i]  + aoff);
                #pragma unroll
                for (int jp = 0; jp < 4; ++jp) ldsm_x4(fb[0][jp], sBn + bBase[jp] + boff);
            }
            #pragma unroll
            for (int i = 0; i < 4; ++i)
                #pragma unroll
                for (int j = 0; j < 8; ++j)
                    mma_f16(acc[i][j], fa[1][i], &fb[1][j >> 1][(j & 1) * 2]);

            __syncwarp();
            if (lid == 0) MBARRIER_ARRIVE(sbase + 64 + 8 * s);

            const long pf = gi + STAGES - 1;
            if (tid == 0 && pf < totIt) {
                const int s2 = (int)(pf & (STAGES - 1));
                if (pf >= STAGES)
                    MBARRIER_WAIT_PARITY(sbase + 64 + 8 * s2, (uint32_t)(((pf >> 2) - 1) & 1));
                const __half *pa, *pb;
                panels(pf, pa, pb);
                const uint32_t st = sbase + HDR + s2 * STG;
                MBARRIER_EXPECT_TX(sbase + 8 * s2, STG);
                BULK_G2S(st,        pa, A_ST, sbase + 8 * s2);
                BULK_G2S(st + A_ST, pb, B_ST, sbase + 8 * s2);
            }
        }

        const int jb0 = n0 + warpN * 64;
        #pragma unroll
        for (int j = 0; j < 8; ++j) {
            const int col = jb0 + j * 8 + 2 * tg;
            const float bb0 = bias1[col], bb1 = bias1[col + 1];
            #pragma unroll
            for (int i = 0; i < 4; ++i) {
                const long r0 = m0 + warpM * 64 + i * 16 + g;
                #pragma unroll
                for (int h = 0; h < 2; ++h) {
                    const long r = r0 + 8 * h;
                    *reinterpret_cast<float2*>(C + (size_t)r * N + col) =
                        make_float2(acc[i][j][2 * h + 0] + bb0,
                                    acc[i][j][2 * h + 1] + bb1);
                }
            }
        }
    }
}

// ----------------------------------------------------------------------------
// Host launcher
// ----------------------------------------------------------------------------
extern "C" void kernel_launch(void* const* d_in, const int* in_sizes, int n_in,
                              void* d_out, int out_size)
{
    const float* x    = (const float*)d_in[0];
    const float* W1   = (const float*)d_in[1];
    const float* b1   = (const float*)d_in[2];
    const float* W2   = (const float*)d_in[3];
    const float* bih  = (const float*)d_in[4];
    const float* bhh  = (const float*)d_in[5];
    const float* W3   = (const float*)d_in[6];
    const float* b3   = (const float*)d_in[7];
    float* out = (float*)d_out;

    __half *gx, *gh, *go, *gw1, *gw2, *gw3;
    cudaGetSymbolAddress((void**)&gx,  g_x);
    cudaGetSymbolAddress((void**)&gh,  g_h);
    cudaGetSymbolAddress((void**)&go,  g_o);
    cudaGetSymbolAddress((void**)&gw1, g_w1);
    cudaGetSymbolAddress((void**)&gw2, g_w2);
    cudaGetSymbolAddress((void**)&gw3, g_w3);

    cudaFuncSetAttribute(gemm_f16_kernel<true, true>,
                         cudaFuncAttributeMaxDynamicSharedMemorySize, SMEM_TOTAL);
    cudaFuncSetAttribute(gemm_f16_hoist_kernel,
                         cudaFuncAttributeMaxDynamicSharedMemorySize, SMEM_TOTAL);
    cudaFuncSetAttribute(gemm_f16_rem64_kernel,
                         cudaFuncAttributeMaxDynamicSharedMemorySize, SMEM_REM);

    int nsm = 148;
    cudaDeviceGetAttribute(&nsm, cudaDevAttrMultiProcessorCount, 0);

    // fused pre-pass: fp32 -> fp16 into swizzled panels (single launch)
    {
        CvtSeg s0 = { x,  gx,  (int)(MTOK * (long)DIN / 8), 7, 7 };   // RP=128
        CvtSeg s1 = { W1, gw1, (int)((long)DH * DIN / 8),   7, 8 };   // RP=256
        CvtSeg s2 = { W2, gw2, (int)((long)DH * DH / 8),    8, 8 };
        CvtSeg s3 = { W3, gw3, (int)((long)DACT * DH / 8),  8, 8 };
        const int total = s0.ng + s1.ng + s2.ng + s3.ng;
        cvt_all_kernel<<<2048, 512>>>(s0, s1, s2, s3, total);
    }

    const int Mtiles = (int)(MTOK / BM);   // 256
    const int T12 = Mtiles * (DH / BN);    // 2048 tiles for GEMM1/2
    const int main12 = (T12 / nsm) * nsm;  // zero-tail main part
    const int rem12  = T12 - main12;       // remainder tiles -> 2x halves

    // GEMM1: h = relu(x @ W1^T + b1) -> fp16 panels   (KT=16)
    gemm_f16_kernel<true, true><<<nsm, NTHR, SMEM_TOTAL>>>(
        gx, gw1, gh, b1, nullptr, DH, 4, 3, main12);
    if (rem12 > 0)
        gemm_f16_rem64_kernel<<<nsm, NTHR, SMEM_REM>>>(
            gx, gw1, gh, b1, nullptr, DH, 4, 3, main12, rem12 * 2);

    // GEMM2: o = relu(h @ W2^T + bih + bhh) -> fp16 panels (KT=32)
    gemm_f16_kernel<true, true><<<nsm, NTHR, SMEM_TOTAL>>>(
        gh, gw2, go, bih, bhh, DH, 5, 3, main12);
    if (rem12 > 0)
        gemm_f16_rem64_kernel<<<nsm, NTHR, SMEM_REM>>>(
            gh, gw2, go, bih, bhh, DH, 5, 3, main12, rem12 * 2);

    // GEMM3: y = o @ W3^T + b3 -> fp32 row-major (KT=32, hoist)
    gemm_f16_hoist_kernel<<<nsm, NTHR, SMEM_TOTAL>>>(
        go, gw3, out, b3, DACT, 5, 2, Mtiles * (DACT / BN));

    (void)in_sizes; (void)n_in; (void)out_size;
}

// round 16
// speedup vs baseline: 2.0074x; 1.0062x over previous
#include <cuda_runtime.h>
#include <cuda_fp16.h>
#include <cstdint>

// ----------------------------------------------------------------------------
// R15 = R14 + PDL overlap of remainder waves + GEMM3 wave-split.
// Chain: cvt -> G1main -> G1rem(PDL) -> G2main(PDL) -> G2rem(PDL)
//            -> G3main(PDL) -> G3rem(PDL)
// Each PDL kernel skips waiting ONLY for its immediate predecessor (verified
// independent by m-block coverage); all earlier work still completes first.
//   main12 = 1976 tiles -> h/o m-blocks 0..246; rem -> 247..255.
//   G3 main = 912 tiles reads o m-blocks 0..227 (subset of G2main's output).
//
//   h = relu(x @ W_init^T + b_init)        M=32768 N=2048 K=1024
//   o = relu(h @ W_ih^T  + b_ih + b_hh)    M=32768 N=2048 K=2048
//   y =       o @ W_final^T + b_final      M=32768 N=1024 K=2048
// ----------------------------------------------------------------------------

#define DINLINE __device__ __forceinline__

static constexpr int DIN  = 1024;
static constexpr int DH   = 2048;
static constexpr int DACT = 1024;
static constexpr long MTOK = 32768;

static constexpr int BM = 128;
static constexpr int BN = 256;
static constexpr int BK = 64;            // 128B rows
static constexpr int STAGES = 4;
static constexpr int NTHR = 256;

static constexpr int A_ST = BM * BK * 2;         // 16384 B
static constexpr int B_ST = BN * BK * 2;         // 32768 B
static constexpr int STG  = A_ST + B_ST;         // 49152 B
static constexpr int HDR  = 1024;
static constexpr int SMEM_TOTAL = HDR + STAGES * STG;   // 197632

// rem kernels (BM=64)
static constexpr int A_HST = 64 * BK * 2;        // 8192 B
static constexpr int STG_H = A_HST + B_ST;       // 40960 B
static constexpr int SMEM_REM = HDR + STAGES * STG_H;   // 164864

DINLINE uint32_t smem_u32(const void* p) {
    uint32_t a;
    asm("{ .reg .u64 t; cvta.to.shared.u64 t, %1; cvt.u32.u64 %0, t; }"
        : "=r"(a) : "l"(p));
    return a;
}

// all CTAs execute this early so PDL-attributed successors may begin filling
// SMs as this kernel drains. No successor reads this kernel's output unless it
// is >=2 launches behind (full completion enforced by PDL semantics).
#define PDL_TRIGGER() asm volatile("griddepcontrol.launch_dependents;" ::: "memory")

#define MBARRIER_INIT(addr, cnt) \
    asm volatile("mbarrier.init.shared.b64 [%0], %1;" :: "r"(addr), "r"(cnt) : "memory")
#define MBARRIER_ARRIVE(addr) \
    asm volatile("mbarrier.arrive.shared.b64 _, [%0];" :: "r"(addr) : "memory")
#define MBARRIER_EXPECT_TX(addr, n) \
    asm volatile("mbarrier.arrive.expect_tx.shared.b64 _, [%0], %1;" :: "r"(addr), "r"(n) : "memory")

#define MBARRIER_WAIT_PARITY(mbar_smem_addr, phase_parity) do { \
    uint32_t _mbar = (uint32_t)(mbar_smem_addr); \
    uint32_t _parity = (uint32_t)(phase_parity); \
    uint32_t _done; \
    asm volatile( \
        "{\n\t" \
        ".reg .pred p;\n\t" \
        "mbarrier.try_wait.parity.shared.b64 p, [%1], %2;\n\t" \
        "selp.b32 %0, 1, 0, p;\n\t" \
        "}" \
        : "=r"(_done) : "r"(_mbar), "r"(_parity) : "memory"); \
    if (!_done) { \
        asm volatile( \
            "{\n\t" \
            ".reg .pred P1;\n\t" \
            "WAIT_LOOP_%=:\n\t" \
            "mbarrier.try_wait.parity.shared.b64 P1, [%0], %1, 0x989680;\n\t" \
            "@P1 bra.uni WAIT_DONE_%=;\n\t" \
            "bra.uni WAIT_LOOP_%=;\n\t" \
            "WAIT_DONE_%=:\n\t" \
            "}" \
            :: "r"(_mbar), "r"(_parity) : "memory"); \
    } \
} while(0)

#define BULK_G2S(dst, src, sz, mbar) \
    asm volatile("cp.async.bulk.shared::cta.global.mbarrier::complete_tx::bytes [%0], [%1], %2, [%3];" \
        :: "r"((uint32_t)(dst)), "l"(src), "r"((uint32_t)(sz)), "r"((uint32_t)(mbar)) : "memory")

DINLINE void ldsm_x4(uint32_t* r, uint32_t addr) {
    asm volatile("ldmatrix.sync.aligned.m8n8.x4.shared.b16 {%0,%1,%2,%3}, [%4];"
        : "=r"(r[0]), "=r"(r[1]), "=r"(r[2]), "=r"(r[3]) : "r"(addr));
}

DINLINE void mma_f16(float* c, const uint32_t* a, const uint32_t* b) {
    asm volatile(
        "mma.sync.aligned.m16n8k16.row.col.f32.f16.f16.f32 "
        "{%0,%1,%2,%3}, {%4,%5,%6,%7}, {%8,%9}, {%0,%1,%2,%3};"
        : "+f"(c[0]), "+f"(c[1]), "+f"(c[2]), "+f"(c[3])
        : "r"(a[0]), "r"(a[1]), "r"(a[2]), "r"(a[3]), "r"(b[0]), "r"(b[1]));
}

// ----------------------------------------------------------------------------
// Scratch (static device allocations -- allowed). All in swizzled panel layout.
// ----------------------------------------------------------------------------
__device__ __half g_x [MTOK * DIN];
__device__ __half g_h [MTOK * DH];
__device__ __half g_o [MTOK * DH];
__device__ __half g_w1[(long)DH * DIN];
__device__ __half g_w2[(long)DH * DH];
__device__ __half g_w3[(long)DACT * DH];

// ----------------------------------------------------------------------------
// Fused fp32 -> fp16 + tile/swizzle pre-pass (all four tensors, one launch).
// ----------------------------------------------------------------------------
struct CvtSeg {
    const float* in;
    __half* out;
    int ng;        // granule count
    int kshift;    // log2(K/8)
    int rplog;     // log2(RP)
};

__global__ void __launch_bounds__(512, 2)
cvt_all_kernel(CvtSeg s0, CvtSeg s1, CvtSeg s2, CvtSeg s3, int total)
{
    for (int gi0 = blockIdx.x * blockDim.x + threadIdx.x; gi0 < total;
         gi0 += gridDim.x * blockDim.x) {
        CvtSeg s; int gi = gi0;
        if (gi < s0.ng) s = s0;
        else {
            gi -= s0.ng;
            if (gi < s1.ng) s = s1;
            else {
                gi -= s1.ng;
                if (gi < s2.ng) s = s2;
                else { gi -= s2.ng; s = s3; }
            }
        }
        const int gperrow = 1 << s.kshift;
        const int c8 = gi & (gperrow - 1);
        const int r  = gi >> s.kshift;
        const float4* f4 = reinterpret_cast<const float4*>(s.in);
        float4 v0 = f4[2 * (size_t)gi], v1 = f4[2 * (size_t)gi + 1];
        __half2 h0 = __floats2half2_rn(v0.x, v0.y), h1 = __floats2half2_rn(v0.z, v0.w);
        __half2 h2 = __floats2half2_rn(v1.x, v1.y), h3 = __floats2half2_rn(v1.z, v1.w);
        uint4 o = make_uint4(*reinterpret_cast<uint32_t*>(&h0), *reinterpret_cast<uint32_t*>(&h1),
                             *reinterpret_cast<uint32_t*>(&h2), *reinterpret_cast<uint32_t*>(&h3));
        const int rp = 1 << s.rplog;
        const size_t panel = (size_t)(r >> s.rplog) * (gperrow >> 3) + (c8 >> 3);
        const size_t gip   = (size_t)(r & (rp - 1)) * 8 + ((c8 & 7) ^ (r & 7));
        reinterpret_cast<uint4*>(s.out)[panel * ((size_t)rp * 8) + gip] = o;
    }
}

// ----------------------------------------------------------------------------
// Kernel A (R7 body): persistent GEMM, fp16 panel out + relu. GEMM1/2 main.
// ----------------------------------------------------------------------------
template <bool HALF_OUT, bool RELU>
__global__ void __launch_bounds__(NTHR, 1)
gemm_f16_kernel(const __half* __restrict__ A, const __half* __restrict__ Bw,
                void* __restrict__ Cv,
                const float* __restrict__ bias1, const float* __restrict__ bias2,
                int N, int ktlog, int ntlog, int Ttiles)
{
    extern __shared__ char smem[];
    const uint32_t sbase = smem_u32(smem);
    const int tid = threadIdx.x;
    const int wid = tid >> 5;
    const int lid = tid & 31;
    const int g   = lid >> 2;
    const int tg  = lid & 3;
    const int bid = blockIdx.x;
    const int grid = gridDim.x;
    const int KT = 1 << ktlog;
    const int ntmask = (1 << ntlog) - 1;

    PDL_TRIGGER();

    const int warpM = wid >> 2;
    const int warpN = wid & 3;

    if (tid == 0) {
        #pragma unroll
        for (int s = 0; s < STAGES; ++s) {
            MBARRIER_INIT(sbase + 8 * s, 1);
            MBARRIER_INIT(sbase + 64 + 8 * s, 8);
        }
    }
    __syncthreads();

    const int nMy = (bid < Ttiles) ? ((Ttiles - bid - 1) / grid + 1) : 0;
    if (nMy == 0) return;
    const long totIt = (long)nMy << ktlog;

    auto panels = [&](long q, const __half*& pa, const __half*& pb) {
        const int tIdx = (int)(q >> ktlog);
        const int kt   = (int)(q & (KT - 1));
        const int tile = bid + tIdx * grid;
        const int mtq  = tile >> ntlog;
        const int ntq  = tile & ntmask;
        pa = A  + ((size_t)mtq * KT + kt) * (A_ST / 2);
        pb = Bw + ((size_t)ntq * KT + kt) * (B_ST / 2);
    };

    if (tid == 0) {
        #pragma unroll
        for (int s = 0; s < STAGES - 1; ++s) {
            if (s < totIt) {
                const __half *pa, *pb;
                panels(s, pa, pb);
                const uint32_t st = sbase + HDR + s * STG;
                MBARRIER_EXPECT_TX(sbase + 8 * s, STG);
                BULK_G2S(st,        pa, A_ST, sbase + 8 * s);
                BULK_G2S(st + A_ST, pb, B_ST, sbase + 8 * s);
            }
        }
    }

    const int lm   = lid >> 3;
    const int aRow = warpM * 64 + ((lm & 1) << 3) + (lid & 7);
    const int asel = lm >> 1;
    const int aXor = aRow & 7;
    const int bRow = warpN * 64 + ((lm >> 1) << 3) + (lid & 7);
    const int bsel = lm & 1;
    const int bXor = bRow & 7;
    uint32_t aBase[4], bBase[4];
    #pragma unroll
    for (int i = 0; i < 4; ++i) aBase[i] = (uint32_t)(aRow + i * 16) * 128;
    #pragma unroll
    for (int jp = 0; jp < 4; ++jp) bBase[jp] = (uint32_t)(bRow + jp * 16) * 128;

    for (int tl = 0; tl < nMy; ++tl) {
        const int tile = bid + tl * grid;
        const int mt = tile >> ntlog;
        const int nt = tile & ntmask;
        const long m0 = (long)mt * BM;
        const int  n0 = nt * BN;
        const long gbase = (long)tl << ktlog;

        float acc[4][8][4];
        #pragma unroll
        for (int i = 0; i < 4; ++i)
            #pragma unroll
            for (int j = 0; j < 8; ++j)
                #pragma unroll
                for (int e = 0; e < 4; ++e) acc[i][j][e] = 0.0f;

        for (int kt = 0; kt < KT; ++kt) {
            const long gi = gbase + kt;
            const int s = (int)(gi & (STAGES - 1));

            MBARRIER_WAIT_PARITY(sbase + 8 * s, (uint32_t)((gi >> 2) & 1));

            const uint32_t sA = sbase + HDR + s * STG;
            const uint32_t sB = sA + A_ST;

            uint32_t fa[2][4][4], fb[2][4][4];
            {
                const uint32_t aoff = (uint32_t)(((0 + asel) ^ aXor) << 4);
                const uint32_t boff = (uint32_t)(((0 + bsel) ^ bXor) << 4);
                #pragma unroll
                for (int i = 0; i < 4; ++i)    ldsm_x4(fa[0][i],  sA + aBase[i]  + aoff);
                #pragma unroll
                for (int jp = 0; jp < 4; ++jp) ldsm_x4(fb[0][jp], sB + bBase[jp] + boff);
            }

            #pragma unroll
            for (int kk = 0; kk < 4; ++kk) {
                const int cur = kk & 1, nxt = cur ^ 1;
                if (kk < 3) {
                    const uint32_t aoff = (uint32_t)((((kk + 1) * 2 + asel) ^ aXor) << 4);
                    const uint32_t boff = (uint32_t)((((kk + 1) * 2 + bsel) ^ bXor) << 4);
                    #pragma unroll
                    for (int i = 0; i < 4; ++i)    ldsm_x4(fa[nxt][i],  sA + aBase[i]  + aoff);
                    #pragma unroll
                    for (int jp = 0; jp < 4; ++jp) ldsm_x4(fb[nxt][jp], sB + bBase[jp] + boff);
                }
                #pragma unroll
                for (int i = 0; i < 4; ++i)
                    #pragma unroll
                    for (int j = 0; j < 8; ++j)
                        mma_f16(acc[i][j], fa[cur][i], &fb[cur][j >> 1][(j & 1) * 2]);
            }

            const long pf = gi + STAGES - 1;
            if (tid == 0 && pf < totIt) {
                const int s2 = (int)(pf & (STAGES - 1));
                if (pf >= STAGES)
                    MBARRIER_WAIT_PARITY(sbase + 64 + 8 * s2, (uint32_t)(((pf >> 2) - 1) & 1));
                const __half *pa, *pb;
                panels(pf, pa, pb);
                const uint32_t st = sbase + HDR + s2 * STG;
                MBARRIER_EXPECT_TX(sbase + 8 * s2, STG);
                BULK_G2S(st,        pa, A_ST, sbase + 8 * s2);
                BULK_G2S(st + A_ST, pb, B_ST, sbase + 8 * s2);
            }

            __syncwarp();
            if (lid == 0) MBARRIER_ARRIVE(sbase + 64 + 8 * s);
        }

        const bool has2 = (bias2 != nullptr);
        const int jb0 = n0 + warpN * 64;

        #pragma unroll
        for (int j = 0; j < 8; ++j) {
            const int col = jb0 + j * 8 + 2 * tg;
            float bb0 = bias1[col], bb1 = bias1[col + 1];
            if (has2) { bb0 += bias2[col]; bb1 += bias2[col + 1]; }
            #pragma unroll
            for (int i = 0; i < 4; ++i) {
                const long r0 = m0 + warpM * 64 + i * 16 + g;
                #pragma unroll
                for (int h = 0; h < 2; ++h) {
                    const long r = r0 + 8 * h;
                    float v0 = acc[i][j][2 * h + 0] + bb0;
                    float v1 = acc[i][j][2 * h + 1] + bb1;
                    if (RELU) { v0 = fmaxf(v0, 0.0f); v1 = fmaxf(v1, 0.0f); }
                    if (HALF_OUT) {
                        __half2 hv = __floats2half2_rn(v0, v1);
                        const size_t panel = ((size_t)(r >> 7) * (N >> 6) + (col >> 6)) << 13;
                        const size_t off = panel + (size_t)((int)(r & 127)) * 64
                                         + (size_t)(((((col >> 3) & 7) ^ ((int)r & 7)) << 3) + (col & 7));
                        *reinterpret_cast<uint32_t*>((__half*)Cv + off) =
                            *reinterpret_cast<uint32_t*>(&hv);
                    } else {
                        *reinterpret_cast<float2*>((float*)Cv + (size_t)r * N + col) =
                            make_float2(v0, v1);
                    }
                }
            }
        }
    }
}

// ----------------------------------------------------------------------------
// Kernel R16 (BM=64): remainder halves, fp16 panel out + relu. GEMM1/2 rem.
// ----------------------------------------------------------------------------
__global__ void __launch_bounds__(NTHR, 1)
gemm_f16_rem64_kernel(const __half* __restrict__ A, const __half* __restrict__ Bw,
                      __half* __restrict__ Cv,
                      const float* __restrict__ bias1, const float* __restrict__ bias2,
                      int N, int ktlog, int ntlog, int tileBase, int njobs)
{
    extern __shared__ char smem[];
    const uint32_t sbase = smem_u32(smem);
    const int tid = threadIdx.x;
    const int wid = tid >> 5;
    const int lid = tid & 31;
    const int g   = lid >> 2;
    const int tg  = lid & 3;
    const int bid = blockIdx.x;
    const int grid = gridDim.x;
    const int KT = 1 << ktlog;
    const int ntmask = (1 << ntlog) - 1;

    PDL_TRIGGER();

    const int warpM = wid >> 2;      // 0..1 (32-row slabs)
    const int warpN = wid & 3;

    if (tid == 0) {
        #pragma unroll
        for (int s = 0; s < STAGES; ++s) {
            MBARRIER_INIT(sbase + 8 * s, 1);
            MBARRIER_INIT(sbase + 64 + 8 * s, 8);
        }
    }
    __syncthreads();

    const int nMy = (bid < njobs) ? ((njobs - bid - 1) / grid + 1) : 0;
    if (nMy == 0) return;
    const long totIt = (long)nMy << ktlog;

    auto panels = [&](long q, const __half*& pa, const __half*& pb) {
        const int jIdx = (int)(q >> ktlog);
        const int kt   = (int)(q & (KT - 1));
        const int job  = bid + jIdx * grid;
        const int tile = tileBase + (job >> 1);
        const int mh   = job & 1;
        const int mtq  = tile >> ntlog;
        const int ntq  = tile & ntmask;
        pa = A  + ((size_t)mtq * KT + kt) * (A_ST / 2) + (size_t)mh * (A_HST / 2);
        pb = Bw + ((size_t)ntq * KT + kt) * (B_ST / 2);
    };

    if (tid == 0) {
        #pragma unroll
        for (int s = 0; s < STAGES - 1; ++s) {
            if (s < totIt) {
                const __half *pa, *pb;
                panels(s, pa, pb);
                const uint32_t st = sbase + HDR + s * STG_H;
                MBARRIER_EXPECT_TX(sbase + 8 * s, STG_H);
                BULK_G2S(st,         pa, A_HST, sbase + 8 * s);
                BULK_G2S(st + A_HST, pb, B_ST,  sbase + 8 * s);
            }
        }
    }

    const int lm   = lid >> 3;
    const int aRow = warpM * 32 + ((lm & 1) << 3) + (lid & 7);
    const int asel = lm >> 1;
    const int aXor = aRow & 7;
    const int bRow = warpN * 64 + ((lm >> 1) << 3) + (lid & 7);
    const int bsel = lm & 1;
    const int bXor = bRow & 7;
    uint32_t aBase[2], bBase[4];
    #pragma unroll
    for (int i = 0; i < 2; ++i) aBase[i] = (uint32_t)(aRow + i * 16) * 128;
    #pragma unroll
    for (int jp = 0; jp < 4; ++jp) bBase[jp] = (uint32_t)(bRow + jp * 16) * 128;

    for (int jl = 0; jl < nMy; ++jl) {
        const int job  = bid + jl * grid;
        const int tile = tileBase + (job >> 1);
        const int mh   = job & 1;
        const int mt = tile >> ntlog;
        const int nt = tile & ntmask;
        const long m0 = (long)mt * BM + (long)mh * 64;
        const int  n0 = nt * BN;
        const long gbase = (long)jl << ktlog;

        float acc[2][8][4];
        #pragma unroll
        for (int i = 0; i < 2; ++i)
            #pragma unroll
            for (int j = 0; j < 8; ++j)
                #pragma unroll
                for (int e = 0; e < 4; ++e) acc[i][j][e] = 0.0f;

        for (int kt = 0; kt < KT; ++kt) {
            const long gi = gbase + kt;
            const int s = (int)(gi & (STAGES - 1));

            MBARRIER_WAIT_PARITY(sbase + 8 * s, (uint32_t)((gi >> 2) & 1));

            const uint32_t sA = sbase + HDR + s * STG_H;
            const uint32_t sB = sA + A_HST;

            uint32_t fa[2][2][4], fb[2][4][4];
            {
                const uint32_t aoff = (uint32_t)(((0 + asel) ^ aXor) << 4);
                const uint32_t boff = (uint32_t)(((0 + bsel) ^ bXor) << 4);
                #pragma unroll
                for (int i = 0; i < 2; ++i)    ldsm_x4(fa[0][i],  sA + aBase[i]  + aoff);
                #pragma unroll
                for (int jp = 0; jp < 4; ++jp) ldsm_x4(fb[0][jp], sB + bBase[jp] + boff);
            }

            #pragma unroll
            for (int kk = 0; kk < 4; ++kk) {
                const int cur = kk & 1, nxt = cur ^ 1;
                if (kk < 3) {
                    const uint32_t aoff = (uint32_t)((((kk + 1) * 2 + asel) ^ aXor) << 4);
                    const uint32_t boff = (uint32_t)((((kk + 1) * 2 + bsel) ^ bXor) << 4);
                    #pragma unroll
                    for (int i = 0; i < 2; ++i)    ldsm_x4(fa[nxt][i],  sA + aBase[i]  + aoff);
                    #pragma unroll
                    for (int jp = 0; jp < 4; ++jp) ldsm_x4(fb[nxt][jp], sB + bBase[jp] + boff);
                }
                #pragma unroll
                for (int i = 0; i < 2; ++i)
                    #pragma unroll
                    for (int j = 0; j < 8; ++j)
                        mma_f16(acc[i][j], fa[cur][i], &fb[cur][j >> 1][(j & 1) * 2]);
            }

            const long pf = gi + STAGES - 1;
            if (tid == 0 && pf < totIt) {
                const int s2 = (int)(pf & (STAGES - 1));
                if (pf >= STAGES)
                    MBARRIER_WAIT_PARITY(sbase + 64 + 8 * s2, (uint32_t)(((pf >> 2) - 1) & 1));
                const __half *pa, *pb;
                panels(pf, pa, pb);
                const uint32_t st = sbase + HDR + s2 * STG_H;
                MBARRIER_EXPECT_TX(sbase + 8 * s2, STG_H);
                BULK_G2S(st,         pa, A_HST, sbase + 8 * s2);
                BULK_G2S(st + A_HST, pb, B_ST,  sbase + 8 * s2);
            }

            __syncwarp();
            if (lid == 0) MBARRIER_ARRIVE(sbase + 64 + 8 * s);
        }

        const bool has2 = (bias2 != nullptr);
        const int jb0 = n0 + warpN * 64;

        #pragma unroll
        for (int j = 0; j < 8; ++j) {
            const int col = jb0 + j * 8 + 2 * tg;
            float bb0 = bias1[col], bb1 = bias1[col + 1];
            if (has2) { bb0 += bias2[col]; bb1 += bias2[col + 1]; }
            #pragma unroll
            for (int i = 0; i < 2; ++i) {
                const long r0 = m0 + warpM * 32 + i * 16 + g;
                #pragma unroll
                for (int h = 0; h < 2; ++h) {
                    const long r = r0 + 8 * h;
                    float v0 = fmaxf(acc[i][j][2 * h + 0] + bb0, 0.0f);
                    float v1 = fmaxf(acc[i][j][2 * h + 1] + bb1, 0.0f);
                    __half2 hv = __floats2half2_rn(v0, v1);
                    const size_t panel = ((size_t)(r >> 7) * (N >> 6) + (col >> 6)) << 13;
                    const size_t off = panel + (size_t)((int)(r & 127)) * 64
                                     + (size_t)(((((col >> 3) & 7) ^ ((int)r & 7)) << 3) + (col & 7));
                    *reinterpret_cast<uint32_t*>(Cv + off) =
                        *reinterpret_cast<uint32_t*>(&hv);
                }
            }
        }
    }
}

// ----------------------------------------------------------------------------
// Kernel R32 (BM=64): remainder halves, fp32 out, no relu. GEMM3 rem.
// ----------------------------------------------------------------------------
__global__ void __launch_bounds__(NTHR, 1)
gemm_f16_rem64_f32_kernel(const __half* __restrict__ A, const __half* __restrict__ Bw,
                          float* __restrict__ C, const float* __restrict__ bias1,
                          int N, int ktlog, int ntlog, int tileBase, int njobs)
{
    extern __shared__ char smem[];
    const uint32_t sbase = smem_u32(smem);
    const int tid = threadIdx.x;
    const int wid = tid >> 5;
    const int lid = tid & 31;
    const int g   = lid >> 2;
    const int tg  = lid & 3;
    const int bid = blockIdx.x;
    const int grid = gridDim.x;
    const int KT = 1 << ktlog;
    const int ntmask = (1 << ntlog) - 1;

    PDL_TRIGGER();

    const int warpM = wid >> 2;
    const int warpN = wid & 3;

    if (tid == 0) {
        #pragma unroll
        for (int s = 0; s < STAGES; ++s) {
            MBARRIER_INIT(sbase + 8 * s, 1);
            MBARRIER_INIT(sbase + 64 + 8 * s, 8);
        }
    }
    __syncthreads();

    const int nMy = (bid < njobs) ? ((njobs - bid - 1) / grid + 1) : 0;
    if (nMy == 0) return;
    const long totIt = (long)nMy << ktlog;

    auto panels = [&](long q, const __half*& pa, const __half*& pb) {
        const int jIdx = (int)(q >> ktlog);
        const int kt   = (int)(q & (KT - 1));
        const int job  = bid + jIdx * grid;
        const int tile = tileBase + (job >> 1);
        const int mh   = job & 1;
        const int mtq  = tile >> ntlog;
        const int ntq  = tile & ntmask;
        pa = A  + ((size_t)mtq * KT + kt) * (A_ST / 2) + (size_t)mh * (A_HST / 2);
        pb = Bw + ((size_t)ntq * KT + kt) * (B_ST / 2);
    };

    if (tid == 0) {
        #pragma unroll
        for (int s = 0; s < STAGES - 1; ++s) {
            if (s < totIt) {
                const __half *pa, *pb;
                panels(s, pa, pb);
                const uint32_t st = sbase + HDR + s * STG_H;
                MBARRIER_EXPECT_TX(sbase + 8 * s, STG_H);
                BULK_G2S(st,         pa, A_HST, sbase + 8 * s);
                BULK_G2S(st + A_HST, pb, B_ST,  sbase + 8 * s);
            }
        }
    }

    const int lm   = lid >> 3;
    const int aRow = warpM * 32 + ((lm & 1) << 3) + (lid & 7);
    const int asel = lm >> 1;
    const int aXor = aRow & 7;
    const int bRow = warpN * 64 + ((lm >> 1) << 3) + (lid & 7);
    const int bsel = lm & 1;
    const int bXor = bRow & 7;
    uint32_t aBase[2], bBase[4];
    #pragma unroll
    for (int i = 0; i < 2; ++i) aBase[i] = (uint32_t)(aRow + i * 16) * 128;
    #pragma unroll
    for (int jp = 0; jp < 4; ++jp) bBase[jp] = (uint32_t)(bRow + jp * 16) * 128;

    for (int jl = 0; jl < nMy; ++jl) {
        const int job  = bid + jl * grid;
        const int tile = tileBase + (job >> 1);
        const int mh   = job & 1;
        const int mt = tile >> ntlog;
        const int nt = tile & ntmask;
        const long m0 = (long)mt * BM + (long)mh * 64;
        const int  n0 = nt * BN;
        const long gbase = (long)jl << ktlog;

        float acc[2][8][4];
        #pragma unroll
        for (int i = 0; i < 2; ++i)
            #pragma unroll
            for (int j = 0; j < 8; ++j)
                #pragma unroll
                for (int e = 0; e < 4; ++e) acc[i][j][e] = 0.0f;

        for (int kt = 0; kt < KT; ++kt) {
            const long gi = gbase + kt;
            const int s = (int)(gi & (STAGES - 1));

            MBARRIER_WAIT_PARITY(sbase + 8 * s, (uint32_t)((gi >> 2) & 1));

            const uint32_t sA = sbase + HDR + s * STG_H;
            const uint32_t sB = sA + A_HST;

            uint32_t fa[2][2][4], fb[2][4][4];
            {
                const uint32_t aoff = (uint32_t)(((0 + asel) ^ aXor) << 4);
                const uint32_t boff = (uint32_t)(((0 + bsel) ^ bXor) << 4);
                #pragma unroll
                for (int i = 0; i < 2; ++i)    ldsm_x4(fa[0][i],  sA + aBase[i]  + aoff);
                #pragma unroll
                for (int jp = 0; jp < 4; ++jp) ldsm_x4(fb[0][jp], sB + bBase[jp] + boff);
            }

            #pragma unroll
            for (int kk = 0; kk < 4; ++kk) {
                const int cur = kk & 1, nxt = cur ^ 1;
                if (kk < 3) {
                    const uint32_t aoff = (uint32_t)((((kk + 1) * 2 + asel) ^ aXor) << 4);
                    const uint32_t boff = (uint32_t)((((kk + 1) * 2 + bsel) ^ bXor) << 4);
                    #pragma unroll
                    for (int i = 0; i < 2; ++i)    ldsm_x4(fa[nxt][i],  sA + aBase[i]  + aoff);
                    #pragma unroll
                    for (int jp = 0; jp < 4; ++jp) ldsm_x4(fb[nxt][jp], sB + bBase[jp] + boff);
                }
                #pragma unroll
                for (int i = 0; i < 2; ++i)
                    #pragma unroll
                    for (int j = 0; j < 8; ++j)
                        mma_f16(acc[i][j], fa[cur][i], &fb[cur][j >> 1][(j & 1) * 2]);
            }

            const long pf = gi + STAGES - 1;
            if (tid == 0 && pf < totIt) {
                const int s2 = (int)(pf & (STAGES - 1));
                if (pf >= STAGES)
                    MBARRIER_WAIT_PARITY(sbase + 64 + 8 * s2, (uint32_t)(((pf >> 2) - 1) & 1));
                const __half *pa, *pb;
                panels(pf, pa, pb);
                const uint32_t st = sbase + HDR + s2 * STG_H;
                MBARRIER_EXPECT_TX(sbase + 8 * s2, STG_H);
                BULK_G2S(st,         pa, A_HST, sbase + 8 * s2);
                BULK_G2S(st + A_HST, pb, B_ST,  sbase + 8 * s2);
            }

            __syncwarp();
            if (lid == 0) MBARRIER_ARRIVE(sbase + 64 + 8 * s);
        }

        const int jb0 = n0 + warpN * 64;
        #pragma unroll
        for (int j = 0; j < 8; ++j) {
            const int col = jb0 + j * 8 + 2 * tg;
            const float bb0 = bias1[col], bb1 = bias1[col + 1];
            #pragma unroll
            for (int i = 0; i < 2; ++i) {
                const long r0 = m0 + warpM * 32 + i * 16 + g;
                #pragma unroll
                for (int h = 0; h < 2; ++h) {
                    const long r = r0 + 8 * h;
                    *reinterpret_cast<float2*>(C + (size_t)r * N + col) =
                        make_float2(acc[i][j][2 * h + 0] + bb0,
                                    acc[i][j][2 * h + 1] + bb1);
                }
            }
        }
    }
}

// ----------------------------------------------------------------------------
// Kernel B (R8 hoist body): persistent GEMM, fp32 out, no relu. GEMM3 main.
// ----------------------------------------------------------------------------
__global__ void __launch_bounds__(NTHR, 1)
gemm_f16_hoist_kernel(const __half* __restrict__ A, const __half* __restrict__ Bw,
                      float* __restrict__ C, const float* __restrict__ bias1,
                      int N, int ktlog, int ntlog, int Ttiles)
{
    extern __shared__ char smem[];
    const uint32_t sbase = smem_u32(smem);
    const int tid = threadIdx.x;
    const int wid = tid >> 5;
    const int lid = tid & 31;
    const int g   = lid >> 2;
    const int tg  = lid & 3;
    const int bid = blockIdx.x;
    const int grid = gridDim.x;
    const int KT = 1 << ktlog;
    const int ntmask = (1 << ntlog) - 1;

    PDL_TRIGGER();

    const int warpM = wid >> 2;
    const int warpN = wid & 3;

    if (tid == 0) {
        #pragma unroll
        for (int s = 0; s < STAGES; ++s) {
            MBARRIER_INIT(sbase + 8 * s, 1);
            MBARRIER_INIT(sbase + 64 + 8 * s, 8);
        }
    }
    __syncthreads();

    const int nMy = (bid < Ttiles) ? ((Ttiles - bid - 1) / grid + 1) : 0;
    if (nMy == 0) return;
    const long totIt = (long)nMy << ktlog;

    auto panels = [&](long q, const __half*& pa, const __half*& pb) {
        const int tIdx = (int)(q >> ktlog);
        const int kt   = (int)(q & (KT - 1));
        const int tile = bid + tIdx * grid;
        const int mtq  = tile >> ntlog;
        const int ntq  = tile & ntmask;
        pa = A  + ((size_t)mtq * KT + kt) * (A_ST / 2);
        pb = Bw + ((size_t)ntq * KT + kt) * (B_ST / 2);
    };

    if (tid == 0) {
        #pragma unroll
        for (int s = 0; s < STAGES - 1; ++s) {
            if (s < totIt) {
                const __half *pa, *pb;
                panels(s, pa, pb);
                const uint32_t st = sbase + HDR + s * STG;
                MBARRIER_EXPECT_TX(sbase + 8 * s, STG);
                BULK_G2S(st,        pa, A_ST, sbase + 8 * s);
                BULK_G2S(st + A_ST, pb, B_ST, sbase + 8 * s);
            }
        }
    }

    const int lm   = lid >> 3;
    const int aRow = warpM * 64 + ((lm & 1) << 3) + (lid & 7);
    const int asel = lm >> 1;
    const int aXor = aRow & 7;
    const int bRow = warpN * 64 + ((lm >> 1) << 3) + (lid & 7);
    const int bsel = lm & 1;
    const int bXor = bRow & 7;
    uint32_t aBase[4], bBase[4];
    #pragma unroll
    for (int i = 0; i < 4; ++i) aBase[i] = (uint32_t)(aRow + i * 16) * 128;
    #pragma unroll
    for (int jp = 0; jp < 4; ++jp) bBase[jp] = (uint32_t)(bRow + jp * 16) * 128;

    uint32_t fa[2][4][4], fb[2][4][4];
    {
        MBARRIER_WAIT_PARITY(sbase + 0, 0);
        const uint32_t sA0 = sbase + HDR;
        const uint32_t sB0 = sA0 + A_ST;
        const uint32_t aoff = (uint32_t)(((0 + asel) ^ aXor) << 4);
        const uint32_t boff = (uint32_t)(((0 + bsel) ^ bXor) << 4);
        #pragma unroll
        for (int i = 0; i < 4; ++i)    ldsm_x4(fa[0][i],  sA0 + aBase[i]  + aoff);
        #pragma unroll
        for (int jp = 0; jp < 4; ++jp) ldsm_x4(fb[0][jp], sB0 + bBase[jp] + boff);
    }

    for (int tl = 0; tl < nMy; ++tl) {
        const int tile = bid + tl * grid;
        const int mt = tile >> ntlog;
        const int nt = tile & ntmask;
        const long m0 = (long)mt * BM;
        const int  n0 = nt * BN;
        const long gbase = (long)tl << ktlog;

        float acc[4][8][4];
        #pragma unroll
        for (int i = 0; i < 4; ++i)
            #pragma unroll
            for (int j = 0; j < 8; ++j)
                #pragma unroll
                for (int e = 0; e < 4; ++e) acc[i][j][e] = 0.0f;

        for (int kt = 0; kt < KT; ++kt) {
            const long gi = gbase + kt;
            const int s = (int)(gi & (STAGES - 1));
            const uint32_t sA = sbase + HDR + s * STG;
            const uint32_t sB = sA + A_ST;

            #pragma unroll
            for (int kk = 0; kk < 3; ++kk) {
                const int cur = kk & 1, nxt = cur ^ 1;
                const uint32_t aoff = (uint32_t)((((kk + 1) * 2 + asel) ^ aXor) << 4);
                const uint32_t boff = (uint32_t)((((kk + 1) * 2 + bsel) ^ bXor) << 4);
                #pragma unroll
                for (int i = 0; i < 4; ++i)    ldsm_x4(fa[nxt][i],  sA + aBase[i]  + aoff);
                #pragma unroll
                for (int jp = 0; jp < 4; ++jp) ldsm_x4(fb[nxt][jp], sB + bBase[jp] + boff);
                #pragma unroll
                for (int i = 0; i < 4; ++i)
                    #pragma unroll
                    for (int j = 0; j < 8; ++j)
                        mma_f16(acc[i][j], fa[cur][i], &fb[cur][j >> 1][(j & 1) * 2]);
            }

            if (gi + 1 < totIt) {
                const int sn = (int)((gi + 1) & (STAGES - 1));
                MBARRIER_WAIT_PARITY(sbase + 8 * sn, (uint32_t)(((gi + 1) >> 2) & 1));
                const uint32_t sAn = sbase + HDR + sn * STG;
                const uint32_t sBn = sAn + A_ST;
                const uint32_t aoff = (uint32_t)(((0 + asel) ^ aXor) << 4);
                const uint32_t boff = (uint32_t)(((0 + bsel) ^ bXor) << 4);
                #pragma unroll
                for (int i = 0; i < 4; ++i)    ldsm_x4(fa[0][i],  sAn + aBase[i]  + aoff);
                #pragma unroll
                for (int jp = 0; jp < 4; ++jp) ldsm_x4(fb[0][jp], sBn + bBase[jp] + boff);
            }
            #pragma unroll
            for (int i = 0; i < 4; ++i)
                #pragma unroll
                for (int j = 0; j < 8; ++j)
                    mma_f16(acc[i][j], fa[1][i], &fb[1][j >> 1][(j & 1) * 2]);

            __syncwarp();
            if (lid == 0) MBARRIER_ARRIVE(sbase + 64 + 8 * s);

            const long pf = gi + STAGES - 1;
            if (tid == 0 && pf < totIt) {
                const int s2 = (int)(pf & (STAGES - 1));
                if (pf >= STAGES)
                    MBARRIER_WAIT_PARITY(sbase + 64 + 8 * s2, (uint32_t)(((pf >> 2) - 1) & 1));
                const __half *pa, *pb;
                panels(pf, pa, pb);
                const uint32_t st = sbase + HDR + s2 * STG;
                MBARRIER_EXPECT_TX(sbase + 8 * s2, STG);
                BULK_G2S(st,        pa, A_ST, sbase + 8 * s2);
                BULK_G2S(st + A_ST, pb, B_ST, sbase + 8 * s2);
            }
        }

        const int jb0 = n0 + warpN * 64;
        #pragma unroll
        for (int j = 0; j < 8; ++j) {
            const int col = jb0 + j * 8 + 2 * tg;
            const float bb0 = bias1[col], bb1 = bias1[col + 1];
            #pragma unroll
            for (int i = 0; i < 4; ++i) {
                const long r0 = m0 + warpM * 64 + i * 16 + g;
                #pragma unroll
                for (int h = 0; h < 2; ++h) {
                    const long r = r0 + 8 * h;
                    *reinterpret_cast<float2*>(C + (size_t)r * N + col) =
                        make_float2(acc[i][j][2 * h + 0] + bb0,
                                    acc[i][j][2 * h + 1] + bb1);
                }
            }
        }
    }
}

// ----------------------------------------------------------------------------
// Host launcher
// ----------------------------------------------------------------------------
template <typename F, typename... Args>
static void launch_ex(F* fn, int grid, int smem, bool pdl, Args... args) {
    cudaLaunchConfig_t cfg = {};
    cfg.gridDim = dim3((unsigned)grid);
    cfg.blockDim = dim3(NTHR);
    cfg.dynamicSmemBytes = (size_t)smem;
    cfg.stream = 0;
    cudaLaunchAttribute at;
    at.id = cudaLaunchAttributeProgrammaticStreamSerialization;
    at.val.programmaticStreamSerializationAllowed = 1;
    if (pdl) { cfg.attrs = &at; cfg.numAttrs = 1; }
    cudaLaunchKernelEx(&cfg, fn, args...);
}

extern "C" void kernel_launch(void* const* d_in, const int* in_sizes, int n_in,
                              void* d_out, int out_size)
{
    const float* x    = (const float*)d_in[0];
    const float* W1   = (const float*)d_in[1];
    const float* b1   = (const float*)d_in[2];
    const float* W2   = (const float*)d_in[3];
    const float* bih  = (const float*)d_in[4];
    const float* bhh  = (const float*)d_in[5];
    const float* W3   = (const float*)d_in[6];
    const float* b3   = (const float*)d_in[7];
    float* out = (float*)d_out;

    __half *gx, *gh, *go, *gw1, *gw2, *gw3;
    cudaGetSymbolAddress((void**)&gx,  g_x);
    cudaGetSymbolAddress((void**)&gh,  g_h);
    cudaGetSymbolAddress((void**)&go,  g_o);
    cudaGetSymbolAddress((void**)&gw1, g_w1);
    cudaGetSymbolAddress((void**)&gw2, g_w2);
    cudaGetSymbolAddress((void**)&gw3, g_w3);

    cudaFuncSetAttribute(gemm_f16_kernel<true, true>,
                         cudaFuncAttributeMaxDynamicSharedMemorySize, SMEM_TOTAL);
    cudaFuncSetAttribute(gemm_f16_hoist_kernel,
                         cudaFuncAttributeMaxDynamicSharedMemorySize, SMEM_TOTAL);
    cudaFuncSetAttribute(gemm_f16_rem64_kernel,
                         cudaFuncAttributeMaxDynamicSharedMemorySize, SMEM_REM);
    cudaFuncSetAttribute(gemm_f16_rem64_f32_kernel,
                         cudaFuncAttributeMaxDynamicSharedMemorySize, SMEM_REM);

    int nsm = 148;
    cudaDeviceGetAttribute(&nsm, cudaDevAttrMultiProcessorCount, 0);

    // fused pre-pass: fp32 -> fp16 into swizzled panels (single launch)
    {
        CvtSeg s0 = { x,  gx,  (int)(MTOK * (long)DIN / 8), 7, 7 };   // RP=128
        CvtSeg s1 = { W1, gw1, (int)((long)DH * DIN / 8),   7, 8 };   // RP=256
        CvtSeg s2 = { W2, gw2, (int)((long)DH * DH / 8),    8, 8 };
        CvtSeg s3 = { W3, gw3, (int)((long)DACT * DH / 8),  8, 8 };
        const int total = s0.ng + s1.ng + s2.ng + s3.ng;
        cvt_all_kernel<<<2048, 512>>>(s0, s1, s2, s3, total);
    }

    const int Mtiles = (int)(MTOK / BM);   // 256
    const int T12 = Mtiles * (DH / BN);    // 2048 tiles GEMM1/2
    const int main12 = (T12 / nsm) * nsm;  // zero-tail main
    const int rem12  = T12 - main12;
    const int T3  = Mtiles * (DACT / BN);  // 1024 tiles GEMM3
    const int main3 = (T3 / nsm) * nsm;
    const int rem3  = T3 - main3;

    // G1 main (normal) -> G1 rem (PDL: independent of G1 main's output layout
    // overlap; writes disjoint h m-blocks)
    launch_ex(&gemm_f16_kernel<true, true>, nsm, SMEM_TOTAL, false,
              (const __half*)gx, (const __half*)gw1, (void*)gh, b1, (const float*)nullptr,
              DH, 4, 3, main12);
    if (rem12 > 0)
        launch_ex(&gemm_f16_rem64_kernel, nsm, SMEM_REM, true,
                  (const __half*)gx, (const __half*)gw1, gh, b1, (const float*)nullptr,
                  DH, 4, 3, main12, rem12 * 2);

    // G2 main (PDL: needs only G1 main, which is prior-to-primary)
    launch_ex(&gemm_f16_kernel<true, true>, nsm, SMEM_TOTAL, true,
              (const __half*)gh, (const __half*)gw2, (void*)go, bih, bhh,
              DH, 5, 3, main12);
    if (rem12 > 0)
        launch_ex(&gemm_f16_rem64_kernel, nsm, SMEM_REM, true,
                  (const __half*)gh, (const __half*)gw2, go, bih, bhh,
                  DH, 5, 3, main12, rem12 * 2);

    // G3 main (PDL: reads o m-blocks 0..227, all from G2 main = prior)
    launch_ex(&gemm_f16_hoist_kernel, nsm, SMEM_TOTAL, true,
              (const __half*)go, (const __half*)gw3, out, b3, DACT, 5, 2, main3);
    if (rem3 > 0)
        launch_ex(&gemm_f16_rem64_f32_kernel, nsm, SMEM_REM, true,
                  (const __half*)go, (const __half*)gw3, out, b3,
                  DACT, 5, 2, main3, rem3 * 2);

    (void)in_sizes; (void)n_in; (void)out_size;
}